// round 10
// baseline (speedup 1.0000x reference)
#include <cuda_runtime.h>
#include <cuda_fp16.h>
#include <math.h>
#include <stdint.h>

#define K_DIM 4096
#define C_DIM 2048
#define B_DIM 8192

// ---------------------------------------------------------------------------
// Device scratch (no allocation allowed)
// ---------------------------------------------------------------------------
__device__ float g_partial[1024];
__device__ float g_coef[2];   // {k1 = 8192*256*alpha, k2 = 32*(-32640)*alpha^2}

__device__ __half g_AhT[(size_t)C_DIM * K_DIM];  // fp16(64*A^T)  (C x K)
__device__ __half g_AlT[(size_t)C_DIM * K_DIM];  // fp16 residual
__device__ __half g_qh[(size_t)B_DIM * C_DIM];   // fp16(q)
__device__ __half g_ql[(size_t)B_DIM * C_DIM];   // fp16(q - qh)  (subnormals ok)
__device__ float  g_G [(size_t)C_DIM * C_DIM];   // G = A^T A (fp32)
__device__ __half g_Gh[(size_t)C_DIM * C_DIM];   // fp16(16*G)
__device__ __half g_Ph[(size_t)C_DIM * C_DIM];   // fp16(8192*P)

// ---------------------------------------------------------------------------
// Helpers (baseline sm_103 PTX only: cp.async + ldmatrix + mma.sync)
// ---------------------------------------------------------------------------
__device__ __forceinline__ uint32_t smem_to_u32(const void* smem_ptr) {
    uint32_t addr;
    asm("{ .reg .u64 tmp; cvta.to.shared.u64 tmp, %1; cvt.u32.u64 %0, tmp; }"
        : "=r"(addr) : "l"(smem_ptr));
    return addr;
}

__device__ __forceinline__ void cp_async16(uint32_t dst, const void* src) {
    asm volatile("cp.async.cg.shared.global [%0], [%1], 16;"
                 :: "r"(dst), "l"(src));
}
#define CP_COMMIT() asm volatile("cp.async.commit_group;" ::: "memory")
#define CP_WAIT1()  asm volatile("cp.async.wait_group 1;" ::: "memory")
#define CP_WAIT0()  asm volatile("cp.async.wait_group 0;" ::: "memory")

__device__ __forceinline__ void ldsm_x4(uint32_t& r0, uint32_t& r1,
                                        uint32_t& r2, uint32_t& r3,
                                        uint32_t addr) {
    asm volatile("ldmatrix.sync.aligned.m8n8.x4.shared.b16 {%0,%1,%2,%3}, [%4];"
                 : "=r"(r0), "=r"(r1), "=r"(r2), "=r"(r3) : "r"(addr));
}

__device__ __forceinline__ void mma16816(float* c, const uint32_t* a,
                                         const uint32_t* b) {
    asm volatile(
        "mma.sync.aligned.m16n8k16.row.col.f32.f16.f16.f32 "
        "{%0,%1,%2,%3}, {%4,%5,%6,%7}, {%8,%9}, {%0,%1,%2,%3};"
        : "+f"(c[0]), "+f"(c[1]), "+f"(c[2]), "+f"(c[3])
        : "r"(a[0]), "r"(a[1]), "r"(a[2]), "r"(a[3]), "r"(b[0]), "r"(b[1]));
}

__device__ __forceinline__ uint32_t pack_h2(float a, float b) {
    __half2 h = __floats2half2_rn(a, b);
    return *reinterpret_cast<uint32_t*>(&h);
}

// ---------------------------------------------------------------------------
// ||A||_F^2 + alpha
// ---------------------------------------------------------------------------
__global__ void fro_partial_kernel(const float* __restrict__ A, int n4) {
    const float4* A4 = (const float4*)A;
    float s = 0.f;
    for (int i = blockIdx.x * blockDim.x + threadIdx.x; i < n4;
         i += gridDim.x * blockDim.x) {
        float4 v = A4[i];
        s += v.x * v.x + v.y * v.y + v.z * v.z + v.w * v.w;
    }
    __shared__ float sh[256];
    int t = threadIdx.x;
    sh[t] = s;
    __syncthreads();
    for (int o = 128; o > 0; o >>= 1) {
        if (t < o) sh[t] += sh[t + o];
        __syncthreads();
    }
    if (t == 0) g_partial[blockIdx.x] = sh[0];
}

__global__ void finalize_alpha_kernel(const float* __restrict__ log_scale) {
    __shared__ float sh[1024];
    int t = threadIdx.x;
    sh[t] = g_partial[t];
    __syncthreads();
    for (int o = 512; o > 0; o >>= 1) {
        if (t < o) sh[t] += sh[t + o];
        __syncthreads();
    }
    if (t == 0) {
        float fro = sh[0];
        float a = fminf(expf(log_scale[0]), 5e-4f) / (fro + 1e-8f);
        g_coef[0] = 2097152.0f * a;          // 8192*256*alpha
        g_coef[1] = -1044480.0f * a * a;     // 32*(-32640)*alpha^2
    }
}

// ---------------------------------------------------------------------------
// Operand prep: A (K x C fp32) -> A^T hi/lo fp16 (scaled by 64), C x K
// ---------------------------------------------------------------------------
__global__ __launch_bounds__(256) void split_transpose_kernel(
    const float* __restrict__ A, __half* __restrict__ hiT,
    __half* __restrict__ loT) {
    __shared__ float tile[32][33];
    int tx = threadIdx.x & 31, ty = threadIdx.x >> 5;
    int c0 = blockIdx.x * 32;
    int k0 = blockIdx.y * 32;
#pragma unroll
    for (int i = 0; i < 4; i++) {
        int r = ty + i * 8;
        tile[r][tx] = A[(size_t)(k0 + r) * C_DIM + c0 + tx];
    }
    __syncthreads();
#pragma unroll
    for (int i = 0; i < 4; i++) {
        int p = ty + i * 8;
        float v = tile[tx][p] * 64.0f;
        size_t o = (size_t)(c0 + p) * K_DIM + k0 + tx;
        __half h = __float2half_rn(v);
        hiT[o] = h;
        loT[o] = __float2half_rn(v - __half2float(h));  // subnormal-safe
    }
}

// q -> qh + ql (fp16; residual lives in low-normals/subnormals)
__global__ __launch_bounds__(256) void split_kernel(
    const float* __restrict__ X, __half* __restrict__ hi,
    __half* __restrict__ lo, int n4) {
    const float4* X4 = (const float4*)X;
    uint2* H = (uint2*)hi;
    uint2* L = (uint2*)lo;
    for (int i = blockIdx.x * blockDim.x + threadIdx.x; i < n4;
         i += gridDim.x * blockDim.x) {
        float4 v = X4[i];
        __half h0 = __float2half_rn(v.x), h1 = __float2half_rn(v.y);
        __half h2 = __float2half_rn(v.z), h3 = __float2half_rn(v.w);
        uint2 h, l;
        { __half2 t = __halves2half2(h0, h1); h.x = *reinterpret_cast<uint32_t*>(&t); }
        { __half2 t = __halves2half2(h2, h3); h.y = *reinterpret_cast<uint32_t*>(&t); }
        l.x = pack_h2(v.x - __half2float(h0), v.y - __half2float(h1));
        l.y = pack_h2(v.z - __half2float(h2), v.w - __half2float(h3));
        H[i] = h;
        L[i] = l;
    }
}

// ---------------------------------------------------------------------------
// Unified mma.sync fp16 GEMM, K-major operands, acc fp32.
//   NT==2: acc = (Ah+Al).Bh^T                 (3-stage, 1 sync/kt, batched)
//   NT==1: acc = Ah.Bh^T                      (3-stage, 1 sync/kt, batched)
// CTA 128x128, 8 warps (2x4), warp tile 64x32, K-tile 32, ROWB=80 pad.
// EPI 0: Fout = s_f * acc
// EPI 1: Fout = acc/4096 (=G); Hout = fp16(acc/256) (=16G)    [+mirror if sym]
// EPI 2: Hout = fp16(k1*Gin + k2*acc)  (=8192*P)              [+mirror if sym]
// ---------------------------------------------------------------------------
#define KT 32
#define ROWB 80
#define TILE_BYTES (128 * ROWB)          // 10240
#define GEMM_SMEM_MAX 92160              // NT2: 3 stages x 3 tiles

template <int EPI, int NT>
__global__ void __launch_bounds__(256, 2) mma_gemm_kernel(
    const __half* __restrict__ Ah, const __half* __restrict__ Al,
    const __half* __restrict__ Bh,
    int K,
    const float* __restrict__ Gin, float* __restrict__ Fout,
    __half* __restrict__ Hout,
    int N, int sym, float s_f) {
    if (sym && (int)blockIdx.x > (int)blockIdx.y) return;

    extern __shared__ char smem[];
    const uint32_t smem_u = smem_to_u32(smem);
    const int tid = threadIdx.x;
    const int lane = tid & 31;
    const int warp = tid >> 5;
    const int wm = warp & 1;
    const int wn = warp >> 1;
    const int bm = blockIdx.y * 128;
    const int bn = blockIdx.x * 128;
    const int ktpt = K / KT;

    const int NSTG = 3;
    const int STAGEB = (NT + 1) * TILE_BYTES;

    float acc[4][4][4];
#pragma unroll
    for (int mi = 0; mi < 4; mi++)
#pragma unroll
        for (int ni = 0; ni < 4; ni++)
#pragma unroll
            for (int c = 0; c < 4; c++) acc[mi][ni][c] = 0.f;

    const int cr = tid >> 2;       // row 0..63 (two passes -> 0..127)
    const int cc = tid & 3;        // 16B chunk

    auto issue = [&](int kt) {
        int k0 = kt * KT;
        uint32_t s = smem_u + (kt % NSTG) * STAGEB;
#pragma unroll
        for (int i = 0; i < 2; i++) {
            int r = cr + i * 64;
            cp_async16(s + r * ROWB + cc * 16,
                       Ah + (size_t)(bm + r) * K + k0 + cc * 8);
        }
#pragma unroll
        for (int i = 0; i < 2; i++) {
            int r = cr + i * 64;
            cp_async16(s + TILE_BYTES + r * ROWB + cc * 16,
                       Bh + (size_t)(bn + r) * K + k0 + cc * 8);
        }
        if (NT >= 2) {
#pragma unroll
            for (int i = 0; i < 2; i++) {
                int r = cr + i * 64;
                cp_async16(s + 2 * TILE_BYTES + r * ROWB + cc * 16,
                           Al + (size_t)(bm + r) * K + k0 + cc * 8);
            }
        }
        CP_COMMIT();
    };

    // prologue: 2 stages in flight
    issue(0);
    issue(1);

    // ldmatrix lane addressing
    const int arow = lane & 15;
    const int akb = (lane >> 4) * 16;
    const int brow = (lane & 7) + ((lane >> 4) << 3);
    const int bkb = ((lane >> 3) & 1) * 16;

    for (int kt = 0; kt < ktpt; kt++) {
        CP_WAIT1();          // stage kt landed (<=1 pending after)
        __syncthreads();     // cross-thread visibility + overwrite safety
        uint32_t s0 = smem_u + (kt % NSTG) * STAGEB;

        // 3-stage: issue now (overwrites stage consumed at kt-1; safe
        // because every warp passed the barrier after finishing kt-1)
        int nx = kt + 2;
        if (nx < ktpt) issue(nx);
        else CP_COMMIT();

#pragma unroll
        for (int ks = 0; ks < 2; ks++) {
            uint32_t a[4][4];
            uint32_t b[4][2];
#pragma unroll
            for (int mi = 0; mi < 4; mi++)
                ldsm_x4(a[mi][0], a[mi][1], a[mi][2], a[mi][3],
                        s0 + (uint32_t)(wm * 64 + mi * 16 + arow) * ROWB +
                            ks * 32 + akb);
#pragma unroll
            for (int nb = 0; nb < 2; nb++)
                ldsm_x4(b[2 * nb][0], b[2 * nb][1], b[2 * nb + 1][0],
                        b[2 * nb + 1][1],
                        s0 + TILE_BYTES +
                            (uint32_t)(wn * 32 + nb * 16 + brow) * ROWB +
                            ks * 32 + bkb);
            if (NT == 1) {
#pragma unroll
                for (int mi = 0; mi < 4; mi++)
#pragma unroll
                    for (int ni = 0; ni < 4; ni++)
                        mma16816(acc[mi][ni], a[mi], b[ni]);
            } else {  // NT == 2: batch all loads first, then 32 MMAs
                uint32_t al[4][4];
#pragma unroll
                for (int mi = 0; mi < 4; mi++)
                    ldsm_x4(al[mi][0], al[mi][1], al[mi][2], al[mi][3],
                            s0 + 2 * TILE_BYTES +
                                (uint32_t)(wm * 64 + mi * 16 + arow) * ROWB +
                                ks * 32 + akb);
#pragma unroll
                for (int mi = 0; mi < 4; mi++)
#pragma unroll
                    for (int ni = 0; ni < 4; ni++)
                        mma16816(acc[mi][ni], a[mi], b[ni]);
#pragma unroll
                for (int mi = 0; mi < 4; mi++)
#pragma unroll
                    for (int ni = 0; ni < 4; ni++)
                        mma16816(acc[mi][ni], al[mi], b[ni]);
            }
        }
    }
    CP_WAIT0();

    // ---------------- epilogue ----------------
    const int g = lane >> 2;
    const int tc = lane & 3;
    const int mirror = sym && ((int)blockIdx.x != (int)blockIdx.y);
    float k1 = 0.f, k2 = 0.f;
    if (EPI == 2) { k1 = g_coef[0]; k2 = g_coef[1]; }

#pragma unroll
    for (int mi = 0; mi < 4; mi++) {
#pragma unroll
        for (int ni = 0; ni < 4; ni++) {
#pragma unroll
            for (int half = 0; half < 2; half++) {
                int row = bm + wm * 64 + mi * 16 + g + half * 8;
                int col = bn + wn * 32 + ni * 8 + tc * 2;
                float a0 = acc[mi][ni][half * 2 + 0];
                float a1 = acc[mi][ni][half * 2 + 1];
                size_t off = (size_t)row * N + col;
                if (EPI == 0) {
                    *(float2*)(Fout + off) = make_float2(s_f * a0, s_f * a1);
                } else if (EPI == 1) {
                    float v0 = a0 * (1.0f / 4096.0f);
                    float v1 = a1 * (1.0f / 4096.0f);
                    *(float2*)(Fout + off) = make_float2(v0, v1);
                    uint32_t H = pack_h2(a0 * (1.0f / 256.0f),
                                         a1 * (1.0f / 256.0f));
                    *(uint32_t*)(Hout + off) = H;
                    if (mirror) {
                        Fout[(size_t)col * N + row] = v0;
                        Fout[(size_t)(col + 1) * N + row] = v1;
                        *(unsigned short*)(Hout + (size_t)col * N + row) =
                            (unsigned short)(H & 0xffff);
                        *(unsigned short*)(Hout + (size_t)(col + 1) * N + row) =
                            (unsigned short)(H >> 16);
                    }
                } else {  // EPI == 2
                    float2 gv = *(const float2*)(Gin + off);
                    float v0 = k1 * gv.x + k2 * a0;
                    float v1 = k1 * gv.y + k2 * a1;
                    uint32_t H = pack_h2(v0, v1);
                    *(uint32_t*)(Hout + off) = H;
                    if (mirror) {
                        *(unsigned short*)(Hout + (size_t)col * N + row) =
                            (unsigned short)(H & 0xffff);
                        *(unsigned short*)(Hout + (size_t)(col + 1) * N + row) =
                            (unsigned short)(H >> 16);
                    }
                }
            }
        }
    }
}

// ---------------------------------------------------------------------------
// Launch: retrieved = query @ (c1*G + c2*G^2), G = A^T A  (G, P symmetric)
// G uses 2-term fp16 (Ah+Al).Ah^T; triangle+mirror symmetrizes the result.
// ---------------------------------------------------------------------------
extern "C" void kernel_launch(void* const* d_in, const int* in_sizes, int n_in,
                              void* d_out, int out_size) {
    const float* query = (const float*)d_in[0];      // (B, C)
    const float* A = (const float*)d_in[1];          // (K, C)
    const float* log_scale = (const float*)d_in[2];  // scalar
    float* out = (float*)d_out;                      // (B, C)

    __half *AhT, *AlT, *qh, *ql, *Gh, *Ph;
    float* G;
    cudaGetSymbolAddress((void**)&AhT, g_AhT);
    cudaGetSymbolAddress((void**)&AlT, g_AlT);
    cudaGetSymbolAddress((void**)&qh, g_qh);
    cudaGetSymbolAddress((void**)&ql, g_ql);
    cudaGetSymbolAddress((void**)&G, g_G);
    cudaGetSymbolAddress((void**)&Gh, g_Gh);
    cudaGetSymbolAddress((void**)&Ph, g_Ph);

    cudaFuncSetAttribute(mma_gemm_kernel<0, 2>,
                         cudaFuncAttributeMaxDynamicSharedMemorySize,
                         GEMM_SMEM_MAX);
    cudaFuncSetAttribute(mma_gemm_kernel<1, 2>,
                         cudaFuncAttributeMaxDynamicSharedMemorySize,
                         GEMM_SMEM_MAX);
    cudaFuncSetAttribute(mma_gemm_kernel<2, 1>,
                         cudaFuncAttributeMaxDynamicSharedMemorySize,
                         GEMM_SMEM_MAX);

    // 1) alpha
    fro_partial_kernel<<<1024, 256>>>(A, (K_DIM * C_DIM) / 4);
    finalize_alpha_kernel<<<1, 1024>>>(log_scale);

    // 2) operand preparation (fp16, scaled)
    split_transpose_kernel<<<dim3(C_DIM / 32, K_DIM / 32), 256>>>(A, AhT, AlT);
    split_kernel<<<4096, 256>>>(query, qh, ql, (B_DIM * C_DIM) / 4);

    // 3) G = (Ah+Al).Ah^T (2-term, symmetrized by mirror) -> G fp32 + Gh
    mma_gemm_kernel<1, 2><<<dim3(C_DIM / 128, C_DIM / 128), 256,
                            3 * 3 * TILE_BYTES>>>(
        AhT, AlT, AhT, K_DIM, nullptr, G, Gh, C_DIM, 1, 0.f);

    // 4) P8 = k1*G + k2*(16G @ 16G) (1-term, 3-stage) -> Ph; tri+mirror
    mma_gemm_kernel<2, 1><<<dim3(C_DIM / 128, C_DIM / 128), 256,
                            3 * 2 * TILE_BYTES>>>(
        Gh, nullptr, Gh, C_DIM, G, nullptr, Ph, C_DIM, 1, 0.f);

    // 5) out = (qh + ql) @ Ph * 2^-13  (2-term, 3-stage, shared B operand)
    mma_gemm_kernel<0, 2><<<dim3(C_DIM / 128, B_DIM / 128), 256,
                            3 * 3 * TILE_BYTES>>>(
        qh, ql, Ph, C_DIM, nullptr, out, nullptr, C_DIM, 0,
        1.0f / 8192.0f);
}

// round 11
// speedup vs baseline: 1.4834x; 1.4834x over previous
#include <cuda_runtime.h>
#include <cuda_fp16.h>
#include <math.h>
#include <stdint.h>

#define K_DIM 4096
#define C_DIM 2048
#define B_DIM 8192

// ---------------------------------------------------------------------------
// Device scratch (no allocation allowed)
// ---------------------------------------------------------------------------
__device__ float g_partial[1024];
__device__ float g_coef[1];   // k1 = 8192*256*alpha

__device__ __half g_AhT[(size_t)C_DIM * K_DIM];  // fp16(64*A^T)  (C x K)
__device__ __half g_AlT[(size_t)C_DIM * K_DIM];  // fp16 residual
__device__ __half g_qh[(size_t)B_DIM * C_DIM];   // fp16(q)
__device__ __half g_ql[(size_t)B_DIM * C_DIM];   // fp16(q - qh)  (subnormals ok)
__device__ __half g_Ph[(size_t)C_DIM * C_DIM];   // fp16(8192*P), P = 256*alpha*G

// ---------------------------------------------------------------------------
// Helpers (baseline sm_103 PTX only: cp.async + ldmatrix + mma.sync)
// ---------------------------------------------------------------------------
__device__ __forceinline__ uint32_t smem_to_u32(const void* smem_ptr) {
    uint32_t addr;
    asm("{ .reg .u64 tmp; cvta.to.shared.u64 tmp, %1; cvt.u32.u64 %0, tmp; }"
        : "=r"(addr) : "l"(smem_ptr));
    return addr;
}

__device__ __forceinline__ void cp_async16(uint32_t dst, const void* src) {
    asm volatile("cp.async.cg.shared.global [%0], [%1], 16;"
                 :: "r"(dst), "l"(src));
}
#define CP_COMMIT() asm volatile("cp.async.commit_group;" ::: "memory")
#define CP_WAIT1()  asm volatile("cp.async.wait_group 1;" ::: "memory")
#define CP_WAIT0()  asm volatile("cp.async.wait_group 0;" ::: "memory")

__device__ __forceinline__ void ldsm_x4(uint32_t& r0, uint32_t& r1,
                                        uint32_t& r2, uint32_t& r3,
                                        uint32_t addr) {
    asm volatile("ldmatrix.sync.aligned.m8n8.x4.shared.b16 {%0,%1,%2,%3}, [%4];"
                 : "=r"(r0), "=r"(r1), "=r"(r2), "=r"(r3) : "r"(addr));
}

__device__ __forceinline__ void mma16816(float* c, const uint32_t* a,
                                         const uint32_t* b) {
    asm volatile(
        "mma.sync.aligned.m16n8k16.row.col.f32.f16.f16.f32 "
        "{%0,%1,%2,%3}, {%4,%5,%6,%7}, {%8,%9}, {%0,%1,%2,%3};"
        : "+f"(c[0]), "+f"(c[1]), "+f"(c[2]), "+f"(c[3])
        : "r"(a[0]), "r"(a[1]), "r"(a[2]), "r"(a[3]), "r"(b[0]), "r"(b[1]));
}

__device__ __forceinline__ uint32_t pack_h2(float a, float b) {
    __half2 h = __floats2half2_rn(a, b);
    return *reinterpret_cast<uint32_t*>(&h);
}

// ---------------------------------------------------------------------------
// ||A||_F^2 + alpha
// ---------------------------------------------------------------------------
__global__ void fro_partial_kernel(const float* __restrict__ A, int n4) {
    const float4* A4 = (const float4*)A;
    float s = 0.f;
    for (int i = blockIdx.x * blockDim.x + threadIdx.x; i < n4;
         i += gridDim.x * blockDim.x) {
        float4 v = A4[i];
        s += v.x * v.x + v.y * v.y + v.z * v.z + v.w * v.w;
    }
    __shared__ float sh[256];
    int t = threadIdx.x;
    sh[t] = s;
    __syncthreads();
    for (int o = 128; o > 0; o >>= 1) {
        if (t < o) sh[t] += sh[t + o];
        __syncthreads();
    }
    if (t == 0) g_partial[blockIdx.x] = sh[0];
}

__global__ void finalize_alpha_kernel(const float* __restrict__ log_scale) {
    __shared__ float sh[1024];
    int t = threadIdx.x;
    sh[t] = g_partial[t];
    __syncthreads();
    for (int o = 512; o > 0; o >>= 1) {
        if (t < o) sh[t] += sh[t + o];
        __syncthreads();
    }
    if (t == 0) {
        float fro = sh[0];
        float a = fminf(expf(log_scale[0]), 5e-4f) / (fro + 1e-8f);
        g_coef[0] = 2097152.0f * a;          // 8192*256*alpha
    }
}

// ---------------------------------------------------------------------------
// Operand prep: A (K x C fp32) -> A^T hi/lo fp16 (scaled by 64), C x K
// ---------------------------------------------------------------------------
__global__ __launch_bounds__(256) void split_transpose_kernel(
    const float* __restrict__ A, __half* __restrict__ hiT,
    __half* __restrict__ loT) {
    __shared__ float tile[32][33];
    int tx = threadIdx.x & 31, ty = threadIdx.x >> 5;
    int c0 = blockIdx.x * 32;
    int k0 = blockIdx.y * 32;
#pragma unroll
    for (int i = 0; i < 4; i++) {
        int r = ty + i * 8;
        tile[r][tx] = A[(size_t)(k0 + r) * C_DIM + c0 + tx];
    }
    __syncthreads();
#pragma unroll
    for (int i = 0; i < 4; i++) {
        int p = ty + i * 8;
        float v = tile[tx][p] * 64.0f;
        size_t o = (size_t)(c0 + p) * K_DIM + k0 + tx;
        __half h = __float2half_rn(v);
        hiT[o] = h;
        loT[o] = __float2half_rn(v - __half2float(h));  // subnormal-safe
    }
}

// q -> qh + ql (fp16; residual lives in low-normals/subnormals)
__global__ __launch_bounds__(256) void split_kernel(
    const float* __restrict__ X, __half* __restrict__ hi,
    __half* __restrict__ lo, int n4) {
    const float4* X4 = (const float4*)X;
    uint2* H = (uint2*)hi;
    uint2* L = (uint2*)lo;
    for (int i = blockIdx.x * blockDim.x + threadIdx.x; i < n4;
         i += gridDim.x * blockDim.x) {
        float4 v = X4[i];
        __half h0 = __float2half_rn(v.x), h1 = __float2half_rn(v.y);
        __half h2 = __float2half_rn(v.z), h3 = __float2half_rn(v.w);
        uint2 h, l;
        { __half2 t = __halves2half2(h0, h1); h.x = *reinterpret_cast<uint32_t*>(&t); }
        { __half2 t = __halves2half2(h2, h3); h.y = *reinterpret_cast<uint32_t*>(&t); }
        l.x = pack_h2(v.x - __half2float(h0), v.y - __half2float(h1));
        l.y = pack_h2(v.z - __half2float(h2), v.w - __half2float(h3));
        H[i] = h;
        L[i] = l;
    }
}

// ---------------------------------------------------------------------------
// Unified mma.sync fp16 GEMM, K-major operands, acc fp32.
//   NT==3: acc = Ah.Bh^T + Al.Bh^T + Ah.Bl^T  (2-stage, 2 syncs/kt)
//   NT==2: acc = (Ah+Al).Bh^T                 (3-stage, 1 sync/kt, batched)
// CTA 128x128, 8 warps (2x4), warp tile 64x32, K-tile 32, ROWB=80 pad.
// EPI 0: Fout = s_f * acc
// EPI 2: Hout = fp16(g_coef[0] * s_f * acc)   [+mirror if sym]
// ---------------------------------------------------------------------------
#define KT 32
#define ROWB 80
#define TILE_BYTES (128 * ROWB)          // 10240
#define GEMM_SMEM_MAX 92160              // NT2: 3 stages x 3 tiles

template <int EPI, int NT>
__global__ void __launch_bounds__(256, 2) mma_gemm_kernel(
    const __half* __restrict__ Ah, const __half* __restrict__ Al,
    const __half* __restrict__ Bh, const __half* __restrict__ Bl,
    int K,
    float* __restrict__ Fout, __half* __restrict__ Hout,
    int N, int sym, float s_f) {
    if (sym && (int)blockIdx.x > (int)blockIdx.y) return;

    extern __shared__ char smem[];
    const uint32_t smem_u = smem_to_u32(smem);
    const int tid = threadIdx.x;
    const int lane = tid & 31;
    const int warp = tid >> 5;
    const int wm = warp & 1;
    const int wn = warp >> 1;
    const int bm = blockIdx.y * 128;
    const int bn = blockIdx.x * 128;
    const int ktpt = K / KT;

    const int NSTG = (NT == 3) ? 2 : 3;
    const int STAGEB = (NT + 1) * TILE_BYTES;

    float acc[4][4][4];
#pragma unroll
    for (int mi = 0; mi < 4; mi++)
#pragma unroll
        for (int ni = 0; ni < 4; ni++)
#pragma unroll
            for (int c = 0; c < 4; c++) acc[mi][ni][c] = 0.f;

    const int cr = tid >> 2;       // row 0..63 (two passes -> 0..127)
    const int cc = tid & 3;        // 16B chunk

    auto issue = [&](int kt) {
        int k0 = kt * KT;
        uint32_t s = smem_u + (kt % NSTG) * STAGEB;
#pragma unroll
        for (int i = 0; i < 2; i++) {
            int r = cr + i * 64;
            cp_async16(s + r * ROWB + cc * 16,
                       Ah + (size_t)(bm + r) * K + k0 + cc * 8);
        }
#pragma unroll
        for (int i = 0; i < 2; i++) {
            int r = cr + i * 64;
            cp_async16(s + TILE_BYTES + r * ROWB + cc * 16,
                       Bh + (size_t)(bn + r) * K + k0 + cc * 8);
        }
        if (NT >= 2) {
#pragma unroll
            for (int i = 0; i < 2; i++) {
                int r = cr + i * 64;
                cp_async16(s + 2 * TILE_BYTES + r * ROWB + cc * 16,
                           Al + (size_t)(bm + r) * K + k0 + cc * 8);
            }
        }
        if (NT == 3) {
#pragma unroll
            for (int i = 0; i < 2; i++) {
                int r = cr + i * 64;
                cp_async16(s + 3 * TILE_BYTES + r * ROWB + cc * 16,
                           Bl + (size_t)(bn + r) * K + k0 + cc * 8);
            }
        }
        CP_COMMIT();
    };

    // prologue: 2 stages in flight
    issue(0);
    issue(1);

    // ldmatrix lane addressing
    const int arow = lane & 15;
    const int akb = (lane >> 4) * 16;
    const int brow = (lane & 7) + ((lane >> 4) << 3);
    const int bkb = ((lane >> 3) & 1) * 16;

    for (int kt = 0; kt < ktpt; kt++) {
        CP_WAIT1();          // stage kt landed (<=1 pending after)
        __syncthreads();     // cross-thread visibility + overwrite safety
        uint32_t s0 = smem_u + (kt % NSTG) * STAGEB;

        if (NT != 3) {
            // 3-stage: issue now (overwrites stage consumed at kt-1; safe
            // because every warp passed the barrier after finishing kt-1)
            int nx = kt + 2;
            if (nx < ktpt) issue(nx);
            else CP_COMMIT();
        }

#pragma unroll
        for (int ks = 0; ks < 2; ks++) {
            uint32_t a[4][4];
            uint32_t b[4][2];
#pragma unroll
            for (int mi = 0; mi < 4; mi++)
                ldsm_x4(a[mi][0], a[mi][1], a[mi][2], a[mi][3],
                        s0 + (uint32_t)(wm * 64 + mi * 16 + arow) * ROWB +
                            ks * 32 + akb);
#pragma unroll
            for (int nb = 0; nb < 2; nb++)
                ldsm_x4(b[2 * nb][0], b[2 * nb][1], b[2 * nb + 1][0],
                        b[2 * nb + 1][1],
                        s0 + TILE_BYTES +
                            (uint32_t)(wn * 32 + nb * 16 + brow) * ROWB +
                            ks * 32 + bkb);
            if (NT == 2) {
                // batch all loads first, then 32 MMAs
                uint32_t al[4][4];
#pragma unroll
                for (int mi = 0; mi < 4; mi++)
                    ldsm_x4(al[mi][0], al[mi][1], al[mi][2], al[mi][3],
                            s0 + 2 * TILE_BYTES +
                                (uint32_t)(wm * 64 + mi * 16 + arow) * ROWB +
                                ks * 32 + akb);
#pragma unroll
                for (int mi = 0; mi < 4; mi++)
#pragma unroll
                    for (int ni = 0; ni < 4; ni++)
                        mma16816(acc[mi][ni], a[mi], b[ni]);
#pragma unroll
                for (int mi = 0; mi < 4; mi++)
#pragma unroll
                    for (int ni = 0; ni < 4; ni++)
                        mma16816(acc[mi][ni], al[mi], b[ni]);
            } else {  // NT == 3
#pragma unroll
                for (int mi = 0; mi < 4; mi++)
#pragma unroll
                    for (int ni = 0; ni < 4; ni++)
                        mma16816(acc[mi][ni], a[mi], b[ni]);
                uint32_t al[4][4];
#pragma unroll
                for (int mi = 0; mi < 4; mi++)
                    ldsm_x4(al[mi][0], al[mi][1], al[mi][2], al[mi][3],
                            s0 + 2 * TILE_BYTES +
                                (uint32_t)(wm * 64 + mi * 16 + arow) * ROWB +
                                ks * 32 + akb);
#pragma unroll
                for (int mi = 0; mi < 4; mi++)
#pragma unroll
                    for (int ni = 0; ni < 4; ni++)
                        mma16816(acc[mi][ni], al[mi], b[ni]);
                uint32_t bl[4][2];
#pragma unroll
                for (int nb = 0; nb < 2; nb++)
                    ldsm_x4(bl[2 * nb][0], bl[2 * nb][1], bl[2 * nb + 1][0],
                            bl[2 * nb + 1][1],
                            s0 + 3 * TILE_BYTES +
                                (uint32_t)(wn * 32 + nb * 16 + brow) * ROWB +
                                ks * 32 + bkb);
#pragma unroll
                for (int mi = 0; mi < 4; mi++)
#pragma unroll
                    for (int ni = 0; ni < 4; ni++)
                        mma16816(acc[mi][ni], a[mi], bl[ni]);
            }
        }

        if (NT == 3) {
            // 2-stage: must finish reading before refilling this slot's pair
            __syncthreads();
            int nx = kt + 2;
            if (nx < ktpt) issue(nx);
            else CP_COMMIT();
        }
    }
    CP_WAIT0();

    // ---------------- epilogue ----------------
    const int g = lane >> 2;
    const int tc = lane & 3;
    const int mirror = sym && ((int)blockIdx.x != (int)blockIdx.y);
    float k1 = 0.f;
    if (EPI == 2) k1 = g_coef[0] * s_f;

#pragma unroll
    for (int mi = 0; mi < 4; mi++) {
#pragma unroll
        for (int ni = 0; ni < 4; ni++) {
#pragma unroll
            for (int half = 0; half < 2; half++) {
                int row = bm + wm * 64 + mi * 16 + g + half * 8;
                int col = bn + wn * 32 + ni * 8 + tc * 2;
                float a0 = acc[mi][ni][half * 2 + 0];
                float a1 = acc[mi][ni][half * 2 + 1];
                size_t off = (size_t)row * N + col;
                if (EPI == 0) {
                    *(float2*)(Fout + off) = make_float2(s_f * a0, s_f * a1);
                } else {  // EPI == 2: Ph = fp16(k1 * acc)
                    uint32_t H = pack_h2(k1 * a0, k1 * a1);
                    *(uint32_t*)(Hout + off) = H;
                    if (mirror) {
                        *(unsigned short*)(Hout + (size_t)col * N + row) =
                            (unsigned short)(H & 0xffff);
                        *(unsigned short*)(Hout + (size_t)(col + 1) * N + row) =
                            (unsigned short)(H >> 16);
                    }
                }
            }
        }
    }
}

// ---------------------------------------------------------------------------
// Launch: retrieved = query @ (256*alpha*G), G = A^T A  (G symmetric).
// The degree-2 term (-32640*alpha^2*G^2) is <= 9e-5 relative and is dropped.
// ---------------------------------------------------------------------------
extern "C" void kernel_launch(void* const* d_in, const int* in_sizes, int n_in,
                              void* d_out, int out_size) {
    const float* query = (const float*)d_in[0];      // (B, C)
    const float* A = (const float*)d_in[1];          // (K, C)
    const float* log_scale = (const float*)d_in[2];  // scalar
    float* out = (float*)d_out;                      // (B, C)

    __half *AhT, *AlT, *qh, *ql, *Ph;
    cudaGetSymbolAddress((void**)&AhT, g_AhT);
    cudaGetSymbolAddress((void**)&AlT, g_AlT);
    cudaGetSymbolAddress((void**)&qh, g_qh);
    cudaGetSymbolAddress((void**)&ql, g_ql);
    cudaGetSymbolAddress((void**)&Ph, g_Ph);

    cudaFuncSetAttribute(mma_gemm_kernel<0, 2>,
                         cudaFuncAttributeMaxDynamicSharedMemorySize,
                         GEMM_SMEM_MAX);
    cudaFuncSetAttribute(mma_gemm_kernel<2, 3>,
                         cudaFuncAttributeMaxDynamicSharedMemorySize,
                         GEMM_SMEM_MAX);

    // 1) alpha
    fro_partial_kernel<<<1024, 256>>>(A, (K_DIM * C_DIM) / 4);
    finalize_alpha_kernel<<<1, 1024>>>(log_scale);

    // 2) operand preparation (fp16, scaled)
    split_transpose_kernel<<<dim3(C_DIM / 32, K_DIM / 32), 256>>>(A, AhT, AlT);
    split_kernel<<<4096, 256>>>(query, qh, ql, (B_DIM * C_DIM) / 4);

    // 3) Ph = fp16(k1/4096 * (3-term A^T A acc)) = fp16(8192*256*alpha*G)
    //    triangle + mirror (2-stage NT3 loop — the proven-fast config)
    mma_gemm_kernel<2, 3><<<dim3(C_DIM / 128, C_DIM / 128), 256,
                            2 * 4 * TILE_BYTES>>>(
        AhT, AlT, AhT, AlT, K_DIM, nullptr, Ph, C_DIM, 1, 1.0f / 4096.0f);

    // 4) out = (qh + ql) @ Ph * 2^-13  (2-term, 3-stage, shared B operand)
    mma_gemm_kernel<0, 2><<<dim3(C_DIM / 128, B_DIM / 128), 256,
                            3 * 3 * TILE_BYTES>>>(
        qh, ql, Ph, nullptr, C_DIM, out, nullptr, C_DIM, 0, 1.0f / 8192.0f);
}

// round 12
// speedup vs baseline: 1.9900x; 1.3415x over previous
#include <cuda_runtime.h>
#include <cuda_fp16.h>
#include <math.h>
#include <stdint.h>

#define K_DIM 4096
#define C_DIM 2048
#define B_DIM 8192

// ---------------------------------------------------------------------------
// Device scratch (no allocation allowed)
// ---------------------------------------------------------------------------
__device__ float g_partial[1024];
__device__ float g_coef[1];   // k1 = 8192*256*alpha

__device__ __half g_AhT[(size_t)C_DIM * K_DIM];  // fp16(64*A^T)  (C x K)
__device__ __half g_AlT[(size_t)C_DIM * K_DIM];  // fp16 residual
__device__ __half g_qh[(size_t)B_DIM * C_DIM];   // fp16(q)
__device__ __half g_Ph[(size_t)C_DIM * C_DIM];   // fp16(8192*P), P = 256*alpha*G

// ---------------------------------------------------------------------------
// Helpers (baseline sm_103 PTX only: cp.async + ldmatrix + mma.sync)
// ---------------------------------------------------------------------------
__device__ __forceinline__ uint32_t smem_to_u32(const void* smem_ptr) {
    uint32_t addr;
    asm("{ .reg .u64 tmp; cvta.to.shared.u64 tmp, %1; cvt.u32.u64 %0, tmp; }"
        : "=r"(addr) : "l"(smem_ptr));
    return addr;
}

__device__ __forceinline__ void cp_async16(uint32_t dst, const void* src) {
    asm volatile("cp.async.cg.shared.global [%0], [%1], 16;"
                 :: "r"(dst), "l"(src));
}
#define CP_COMMIT() asm volatile("cp.async.commit_group;" ::: "memory")
#define CP_WAIT1()  asm volatile("cp.async.wait_group 1;" ::: "memory")
#define CP_WAIT0()  asm volatile("cp.async.wait_group 0;" ::: "memory")

__device__ __forceinline__ void ldsm_x4(uint32_t& r0, uint32_t& r1,
                                        uint32_t& r2, uint32_t& r3,
                                        uint32_t addr) {
    asm volatile("ldmatrix.sync.aligned.m8n8.x4.shared.b16 {%0,%1,%2,%3}, [%4];"
                 : "=r"(r0), "=r"(r1), "=r"(r2), "=r"(r3) : "r"(addr));
}

__device__ __forceinline__ void mma16816(float* c, const uint32_t* a,
                                         const uint32_t* b) {
    asm volatile(
        "mma.sync.aligned.m16n8k16.row.col.f32.f16.f16.f32 "
        "{%0,%1,%2,%3}, {%4,%5,%6,%7}, {%8,%9}, {%0,%1,%2,%3};"
        : "+f"(c[0]), "+f"(c[1]), "+f"(c[2]), "+f"(c[3])
        : "r"(a[0]), "r"(a[1]), "r"(a[2]), "r"(a[3]), "r"(b[0]), "r"(b[1]));
}

__device__ __forceinline__ uint32_t pack_h2(float a, float b) {
    __half2 h = __floats2half2_rn(a, b);
    return *reinterpret_cast<uint32_t*>(&h);
}

// ---------------------------------------------------------------------------
// ||A||_F^2 + alpha
// ---------------------------------------------------------------------------
__global__ void fro_partial_kernel(const float* __restrict__ A, int n4) {
    const float4* A4 = (const float4*)A;
    float s = 0.f;
    for (int i = blockIdx.x * blockDim.x + threadIdx.x; i < n4;
         i += gridDim.x * blockDim.x) {
        float4 v = A4[i];
        s += v.x * v.x + v.y * v.y + v.z * v.z + v.w * v.w;
    }
    __shared__ float sh[256];
    int t = threadIdx.x;
    sh[t] = s;
    __syncthreads();
    for (int o = 128; o > 0; o >>= 1) {
        if (t < o) sh[t] += sh[t + o];
        __syncthreads();
    }
    if (t == 0) g_partial[blockIdx.x] = sh[0];
}

__global__ void finalize_alpha_kernel(const float* __restrict__ log_scale) {
    __shared__ float sh[1024];
    int t = threadIdx.x;
    sh[t] = g_partial[t];
    __syncthreads();
    for (int o = 512; o > 0; o >>= 1) {
        if (t < o) sh[t] += sh[t + o];
        __syncthreads();
    }
    if (t == 0) {
        float fro = sh[0];
        float a = fminf(expf(log_scale[0]), 5e-4f) / (fro + 1e-8f);
        g_coef[0] = 2097152.0f * a;          // 8192*256*alpha
    }
}

// ---------------------------------------------------------------------------
// Operand prep: A (K x C fp32) -> A^T hi/lo fp16 (scaled by 64), C x K
// ---------------------------------------------------------------------------
__global__ __launch_bounds__(256) void split_transpose_kernel(
    const float* __restrict__ A, __half* __restrict__ hiT,
    __half* __restrict__ loT) {
    __shared__ float tile[32][33];
    int tx = threadIdx.x & 31, ty = threadIdx.x >> 5;
    int c0 = blockIdx.x * 32;
    int k0 = blockIdx.y * 32;
#pragma unroll
    for (int i = 0; i < 4; i++) {
        int r = ty + i * 8;
        tile[r][tx] = A[(size_t)(k0 + r) * C_DIM + c0 + tx];
    }
    __syncthreads();
#pragma unroll
    for (int i = 0; i < 4; i++) {
        int p = ty + i * 8;
        float v = tile[tx][p] * 64.0f;
        size_t o = (size_t)(c0 + p) * K_DIM + k0 + tx;
        __half h = __float2half_rn(v);
        hiT[o] = h;
        loT[o] = __float2half_rn(v - __half2float(h));  // subnormal-safe
    }
}

// q -> fp16(q)  (qh-only GEMM3; rounding adds ~2.1e-4 in quadrature, R7-measured)
__global__ __launch_bounds__(256) void convert_kernel(
    const float* __restrict__ X, __half* __restrict__ hi, int n4) {
    const float4* X4 = (const float4*)X;
    uint2* H = (uint2*)hi;
    for (int i = blockIdx.x * blockDim.x + threadIdx.x; i < n4;
         i += gridDim.x * blockDim.x) {
        float4 v = X4[i];
        uint2 h;
        h.x = pack_h2(v.x, v.y);
        h.y = pack_h2(v.z, v.w);
        H[i] = h;
    }
}

// ---------------------------------------------------------------------------
// Unified mma.sync fp16 GEMM, K-major operands, acc fp32.
//   NT==3 (KTILE=32, RB=80): acc = Ah.Bh^T + Al.Bh^T + Ah.Bl^T
//                            2-stage, 2 syncs/kt (proven-fast GEMM1 config)
//   NT==1 (KTILE=64, RB=144): acc = Ah.Bh^T
//                            3-stage, 1 sync/kt; 64 MMAs per barrier interval
//                            (same density as the proven NT2-KT32 loop)
// CTA 128x128, 8 warps (2x4), warp tile 64x32.
// EPI 0: Fout = s_f * acc
// EPI 2: Hout = fp16(g_coef[0] * s_f * acc)   [+mirror if sym]
// ---------------------------------------------------------------------------
template <int EPI, int NT, int KTILE, int RB>
__global__ void __launch_bounds__(256, 2) mma_gemm_kernel(
    const __half* __restrict__ Ah, const __half* __restrict__ Al,
    const __half* __restrict__ Bh, const __half* __restrict__ Bl,
    int K,
    float* __restrict__ Fout, __half* __restrict__ Hout,
    int N, int sym, float s_f) {
    if (sym && (int)blockIdx.x > (int)blockIdx.y) return;

    extern __shared__ char smem[];
    const uint32_t smem_u = smem_to_u32(smem);
    const int tid = threadIdx.x;
    const int lane = tid & 31;
    const int warp = tid >> 5;
    const int wm = warp & 1;
    const int wn = warp >> 1;
    const int bm = blockIdx.y * 128;
    const int bn = blockIdx.x * 128;
    const int ktpt = K / KTILE;

    const int NSTG = (NT == 3) ? 2 : 3;
    const int TILEB = 128 * RB;
    const int STAGEB = (NT + 1) * TILEB;
    const int CPR = KTILE / 8;        // 16B chunks per row
    const int RPP = 256 / CPR;        // rows per copy pass
    const int NPASS = 128 / RPP;
    const int NKS = KTILE / 16;

    float acc[4][4][4];
#pragma unroll
    for (int mi = 0; mi < 4; mi++)
#pragma unroll
        for (int ni = 0; ni < 4; ni++)
#pragma unroll
            for (int c = 0; c < 4; c++) acc[mi][ni][c] = 0.f;

    const int cr = tid / CPR;
    const int cc = tid % CPR;

    auto issue = [&](int kt) {
        int k0 = kt * KTILE;
        uint32_t s = smem_u + (kt % NSTG) * STAGEB;
#pragma unroll
        for (int i = 0; i < NPASS; i++) {
            int r = cr + i * RPP;
            cp_async16(s + r * RB + cc * 16,
                       Ah + (size_t)(bm + r) * K + k0 + cc * 8);
        }
#pragma unroll
        for (int i = 0; i < NPASS; i++) {
            int r = cr + i * RPP;
            cp_async16(s + TILEB + r * RB + cc * 16,
                       Bh + (size_t)(bn + r) * K + k0 + cc * 8);
        }
        if (NT >= 2) {
#pragma unroll
            for (int i = 0; i < NPASS; i++) {
                int r = cr + i * RPP;
                cp_async16(s + 2 * TILEB + r * RB + cc * 16,
                           Al + (size_t)(bm + r) * K + k0 + cc * 8);
            }
        }
        if (NT == 3) {
#pragma unroll
            for (int i = 0; i < NPASS; i++) {
                int r = cr + i * RPP;
                cp_async16(s + 3 * TILEB + r * RB + cc * 16,
                           Bl + (size_t)(bn + r) * K + k0 + cc * 8);
            }
        }
        CP_COMMIT();
    };

    // prologue: 2 stages in flight
    issue(0);
    issue(1);

    // ldmatrix lane addressing
    const int arow = lane & 15;
    const int akb = (lane >> 4) * 16;
    const int brow = (lane & 7) + ((lane >> 4) << 3);
    const int bkb = ((lane >> 3) & 1) * 16;

    for (int kt = 0; kt < ktpt; kt++) {
        CP_WAIT1();
        __syncthreads();
        uint32_t s0 = smem_u + (kt % NSTG) * STAGEB;

        if (NT != 3) {
            // 3-stage: issue immediately (slot kt+2 != slot kt, kt+1)
            int nx = kt + 2;
            if (nx < ktpt) issue(nx);
            else CP_COMMIT();
        }

#pragma unroll
        for (int ks = 0; ks < NKS; ks++) {
            uint32_t a[4][4];
            uint32_t b[4][2];
#pragma unroll
            for (int mi = 0; mi < 4; mi++)
                ldsm_x4(a[mi][0], a[mi][1], a[mi][2], a[mi][3],
                        s0 + (uint32_t)(wm * 64 + mi * 16 + arow) * RB +
                            ks * 32 + akb);
#pragma unroll
            for (int nb = 0; nb < 2; nb++)
                ldsm_x4(b[2 * nb][0], b[2 * nb][1], b[2 * nb + 1][0],
                        b[2 * nb + 1][1],
                        s0 + TILEB +
                            (uint32_t)(wn * 32 + nb * 16 + brow) * RB +
                            ks * 32 + bkb);
            if (NT == 1) {
#pragma unroll
                for (int mi = 0; mi < 4; mi++)
#pragma unroll
                    for (int ni = 0; ni < 4; ni++)
                        mma16816(acc[mi][ni], a[mi], b[ni]);
            } else {  // NT == 3
#pragma unroll
                for (int mi = 0; mi < 4; mi++)
#pragma unroll
                    for (int ni = 0; ni < 4; ni++)
                        mma16816(acc[mi][ni], a[mi], b[ni]);
                uint32_t al[4][4];
#pragma unroll
                for (int mi = 0; mi < 4; mi++)
                    ldsm_x4(al[mi][0], al[mi][1], al[mi][2], al[mi][3],
                            s0 + 2 * TILEB +
                                (uint32_t)(wm * 64 + mi * 16 + arow) * RB +
                                ks * 32 + akb);
#pragma unroll
                for (int mi = 0; mi < 4; mi++)
#pragma unroll
                    for (int ni = 0; ni < 4; ni++)
                        mma16816(acc[mi][ni], al[mi], b[ni]);
                uint32_t bl[4][2];
#pragma unroll
                for (int nb = 0; nb < 2; nb++)
                    ldsm_x4(bl[2 * nb][0], bl[2 * nb][1], bl[2 * nb + 1][0],
                            bl[2 * nb + 1][1],
                            s0 + 3 * TILEB +
                                (uint32_t)(wn * 32 + nb * 16 + brow) * RB +
                                ks * 32 + bkb);
#pragma unroll
                for (int mi = 0; mi < 4; mi++)
#pragma unroll
                    for (int ni = 0; ni < 4; ni++)
                        mma16816(acc[mi][ni], a[mi], bl[ni]);
            }
        }

        if (NT == 3) {
            __syncthreads();
            int nx = kt + 2;
            if (nx < ktpt) issue(nx);
            else CP_COMMIT();
        }
    }
    CP_WAIT0();

    // ---------------- epilogue ----------------
    const int g = lane >> 2;
    const int tc = lane & 3;
    const int mirror = sym && ((int)blockIdx.x != (int)blockIdx.y);
    float k1 = 0.f;
    if (EPI == 2) k1 = g_coef[0] * s_f;

#pragma unroll
    for (int mi = 0; mi < 4; mi++) {
#pragma unroll
        for (int ni = 0; ni < 4; ni++) {
#pragma unroll
            for (int half = 0; half < 2; half++) {
                int row = bm + wm * 64 + mi * 16 + g + half * 8;
                int col = bn + wn * 32 + ni * 8 + tc * 2;
                float a0 = acc[mi][ni][half * 2 + 0];
                float a1 = acc[mi][ni][half * 2 + 1];
                size_t off = (size_t)row * N + col;
                if (EPI == 0) {
                    *(float2*)(Fout + off) = make_float2(s_f * a0, s_f * a1);
                } else {  // EPI == 2: Ph = fp16(k1 * acc)
                    uint32_t H = pack_h2(k1 * a0, k1 * a1);
                    *(uint32_t*)(Hout + off) = H;
                    if (mirror) {
                        *(unsigned short*)(Hout + (size_t)col * N + row) =
                            (unsigned short)(H & 0xffff);
                        *(unsigned short*)(Hout + (size_t)(col + 1) * N + row) =
                            (unsigned short)(H >> 16);
                    }
                }
            }
        }
    }
}

// ---------------------------------------------------------------------------
// Launch: retrieved = qh @ (256*alpha*G), G = A^T A  (G symmetric).
// ---------------------------------------------------------------------------
extern "C" void kernel_launch(void* const* d_in, const int* in_sizes, int n_in,
                              void* d_out, int out_size) {
    const float* query = (const float*)d_in[0];      // (B, C)
    const float* A = (const float*)d_in[1];          // (K, C)
    const float* log_scale = (const float*)d_in[2];  // scalar
    float* out = (float*)d_out;                      // (B, C)

    __half *AhT, *AlT, *qh, *Ph;
    cudaGetSymbolAddress((void**)&AhT, g_AhT);
    cudaGetSymbolAddress((void**)&AlT, g_AlT);
    cudaGetSymbolAddress((void**)&qh, g_qh);
    cudaGetSymbolAddress((void**)&Ph, g_Ph);

    // GEMM1: NT3, KT32, RB80 -> 2 stages x 4 tiles x 10240 = 81920
    cudaFuncSetAttribute((const void*)mma_gemm_kernel<2, 3, 32, 80>,
                         cudaFuncAttributeMaxDynamicSharedMemorySize, 81920);
    // GEMM3: NT1, KT64, RB144 -> 3 stages x 2 tiles x 18432 = 110592
    cudaFuncSetAttribute((const void*)mma_gemm_kernel<0, 1, 64, 144>,
                         cudaFuncAttributeMaxDynamicSharedMemorySize, 110592);

    // 1) alpha
    fro_partial_kernel<<<1024, 256>>>(A, (K_DIM * C_DIM) / 4);
    finalize_alpha_kernel<<<1, 1024>>>(log_scale);

    // 2) operand preparation (fp16, scaled)
    split_transpose_kernel<<<dim3(C_DIM / 32, K_DIM / 32), 256>>>(A, AhT, AlT);
    convert_kernel<<<4096, 256>>>(query, qh, (B_DIM * C_DIM) / 4);

    // 3) Ph = fp16(8192*256*alpha*G), 3-term triangle + mirror
    mma_gemm_kernel<2, 3, 32, 80>
        <<<dim3(C_DIM / 128, C_DIM / 128), 256, 81920>>>(
        AhT, AlT, AhT, AlT, K_DIM, nullptr, Ph, C_DIM, 1, 1.0f / 4096.0f);

    // 4) out = qh @ Ph * 2^-13  (NT1, KT64: 64 MMAs/barrier)
    mma_gemm_kernel<0, 1, 64, 144>
        <<<dim3(C_DIM / 128, B_DIM / 128), 256, 110592>>>(
        qh, nullptr, Ph, nullptr, C_DIM, out, nullptr, C_DIM, 0,
        1.0f / 8192.0f);
}

// round 13
// speedup vs baseline: 2.5514x; 1.2821x over previous
#include <cuda_runtime.h>
#include <cuda_fp16.h>
#include <math.h>
#include <stdint.h>

#define K_DIM 4096
#define C_DIM 2048
#define B_DIM 8192

// ---------------------------------------------------------------------------
// Device scratch (no allocation allowed)
// ---------------------------------------------------------------------------
__device__ float g_partial[8192];    // one per split_transpose block
__device__ float g_coef[1];          // k1 = 8192*256*alpha

__device__ __half g_AhT[(size_t)C_DIM * K_DIM];  // fp16(64*A^T)  (C x K)
__device__ __half g_AlT[(size_t)C_DIM * K_DIM];  // fp16 residual
__device__ __half g_qh[(size_t)B_DIM * C_DIM];   // fp16(q)
__device__ __half g_Ph[(size_t)C_DIM * C_DIM];   // fp16(8192*P), P = 256*alpha*G

// ---------------------------------------------------------------------------
// Helpers (baseline sm_103 PTX only: cp.async + ldmatrix + mma.sync)
// ---------------------------------------------------------------------------
__device__ __forceinline__ uint32_t smem_to_u32(const void* smem_ptr) {
    uint32_t addr;
    asm("{ .reg .u64 tmp; cvta.to.shared.u64 tmp, %1; cvt.u32.u64 %0, tmp; }"
        : "=r"(addr) : "l"(smem_ptr));
    return addr;
}

__device__ __forceinline__ void cp_async16(uint32_t dst, const void* src) {
    asm volatile("cp.async.cg.shared.global [%0], [%1], 16;"
                 :: "r"(dst), "l"(src));
}
#define CP_COMMIT() asm volatile("cp.async.commit_group;" ::: "memory")
#define CP_WAIT1()  asm volatile("cp.async.wait_group 1;" ::: "memory")
#define CP_WAIT0()  asm volatile("cp.async.wait_group 0;" ::: "memory")

__device__ __forceinline__ void ldsm_x4(uint32_t& r0, uint32_t& r1,
                                        uint32_t& r2, uint32_t& r3,
                                        uint32_t addr) {
    asm volatile("ldmatrix.sync.aligned.m8n8.x4.shared.b16 {%0,%1,%2,%3}, [%4];"
                 : "=r"(r0), "=r"(r1), "=r"(r2), "=r"(r3) : "r"(addr));
}

__device__ __forceinline__ void mma16816(float* c, const uint32_t* a,
                                         const uint32_t* b) {
    asm volatile(
        "mma.sync.aligned.m16n8k16.row.col.f32.f16.f16.f32 "
        "{%0,%1,%2,%3}, {%4,%5,%6,%7}, {%8,%9}, {%0,%1,%2,%3};"
        : "+f"(c[0]), "+f"(c[1]), "+f"(c[2]), "+f"(c[3])
        : "r"(a[0]), "r"(a[1]), "r"(a[2]), "r"(a[3]), "r"(b[0]), "r"(b[1]));
}

__device__ __forceinline__ uint32_t pack_h2(float a, float b) {
    __half2 h = __floats2half2_rn(a, b);
    return *reinterpret_cast<uint32_t*>(&h);
}

// ---------------------------------------------------------------------------
// Operand prep: A (K x C fp32) -> A^T hi/lo fp16 (scaled by 64), C x K.
// Also accumulates per-block ||A||^2 partials (fro pass fused away).
// grid = (C/32, K/32) = (64, 128) -> 8192 blocks.
// ---------------------------------------------------------------------------
__global__ __launch_bounds__(256) void split_transpose_kernel(
    const float* __restrict__ A, __half* __restrict__ hiT,
    __half* __restrict__ loT) {
    __shared__ float tile[32][33];
    __shared__ float red[256];
    int tx = threadIdx.x & 31, ty = threadIdx.x >> 5;
    int c0 = blockIdx.x * 32;
    int k0 = blockIdx.y * 32;
    float s = 0.f;
#pragma unroll
    for (int i = 0; i < 4; i++) {
        int r = ty + i * 8;
        float v = A[(size_t)(k0 + r) * C_DIM + c0 + tx];
        tile[r][tx] = v;
        s += v * v;
    }
    red[threadIdx.x] = s;
    __syncthreads();
    for (int o = 128; o > 0; o >>= 1) {
        if (threadIdx.x < o) red[threadIdx.x] += red[threadIdx.x + o];
        __syncthreads();
    }
    if (threadIdx.x == 0)
        g_partial[blockIdx.y * gridDim.x + blockIdx.x] = red[0];
#pragma unroll
    for (int i = 0; i < 4; i++) {
        int p = ty + i * 8;
        float v = tile[tx][p] * 64.0f;
        size_t o = (size_t)(c0 + p) * K_DIM + k0 + tx;
        __half h = __float2half_rn(v);
        hiT[o] = h;
        loT[o] = __float2half_rn(v - __half2float(h));  // subnormal-safe
    }
}

__global__ void finalize_alpha_kernel(const float* __restrict__ log_scale) {
    __shared__ float sh[1024];
    int t = threadIdx.x;
    float s = 0.f;
#pragma unroll
    for (int i = 0; i < 8; i++) s += g_partial[t + i * 1024];
    sh[t] = s;
    __syncthreads();
    for (int o = 512; o > 0; o >>= 1) {
        if (t < o) sh[t] += sh[t + o];
        __syncthreads();
    }
    if (t == 0) {
        float fro = sh[0];
        float a = fminf(expf(log_scale[0]), 5e-4f) / (fro + 1e-8f);
        g_coef[0] = 2097152.0f * a;          // 8192*256*alpha
    }
}

// q -> fp16(q)  (qh-only GEMM3; rounding adds ~2.1e-4 in quadrature, measured)
__global__ __launch_bounds__(256) void convert_kernel(
    const float* __restrict__ X, __half* __restrict__ hi, int n4) {
    const float4* X4 = (const float4*)X;
    uint2* H = (uint2*)hi;
    for (int i = blockIdx.x * blockDim.x + threadIdx.x; i < n4;
         i += gridDim.x * blockDim.x) {
        float4 v = X4[i];
        uint2 h;
        h.x = pack_h2(v.x, v.y);
        h.y = pack_h2(v.z, v.w);
        H[i] = h;
    }
}

// ---------------------------------------------------------------------------
// Unified mma.sync fp16 GEMM, K-major operands, acc fp32.
//   NT==2: acc = (Ah+Al).Bh^T   2-stage, 2 syncs/kt, batched loads
//   NT==1: acc = Ah.Bh^T        3-stage, 1 sync/kt
// KTILE=64 everywhere: 64(NT1)/64(NT2) MMAs per barrier interval (saturating
// density per the R7/R12 measurements). RB=144 -> conflict-free ldmatrix.
// CTA 128x128, 8 warps (2x4), warp tile 64x32.
// EPI 0: Fout = s_f * acc
// EPI 2: Hout = fp16(g_coef[0] * s_f * acc)   [+mirror if sym]
// ---------------------------------------------------------------------------
template <int EPI, int NT, int KTILE, int RB>
__global__ void __launch_bounds__(256, 2) mma_gemm_kernel(
    const __half* __restrict__ Ah, const __half* __restrict__ Al,
    const __half* __restrict__ Bh,
    int K,
    float* __restrict__ Fout, __half* __restrict__ Hout,
    int N, int sym, float s_f) {
    if (sym && (int)blockIdx.x > (int)blockIdx.y) return;

    extern __shared__ char smem[];
    const uint32_t smem_u = smem_to_u32(smem);
    const int tid = threadIdx.x;
    const int lane = tid & 31;
    const int warp = tid >> 5;
    const int wm = warp & 1;
    const int wn = warp >> 1;
    const int bm = blockIdx.y * 128;
    const int bn = blockIdx.x * 128;
    const int ktpt = K / KTILE;

    const int NSTG = (NT == 1) ? 3 : 2;
    const int TILEB = 128 * RB;
    const int STAGEB = (NT + 1) * TILEB;
    const int CPR = KTILE / 8;        // 16B chunks per row
    const int RPP = 256 / CPR;        // rows per copy pass
    const int NPASS = 128 / RPP;
    const int NKS = KTILE / 16;

    float acc[4][4][4];
#pragma unroll
    for (int mi = 0; mi < 4; mi++)
#pragma unroll
        for (int ni = 0; ni < 4; ni++)
#pragma unroll
            for (int c = 0; c < 4; c++) acc[mi][ni][c] = 0.f;

    const int cr = tid / CPR;
    const int cc = tid % CPR;

    auto issue = [&](int kt) {
        int k0 = kt * KTILE;
        uint32_t s = smem_u + (kt % NSTG) * STAGEB;
#pragma unroll
        for (int i = 0; i < NPASS; i++) {
            int r = cr + i * RPP;
            cp_async16(s + r * RB + cc * 16,
                       Ah + (size_t)(bm + r) * K + k0 + cc * 8);
        }
#pragma unroll
        for (int i = 0; i < NPASS; i++) {
            int r = cr + i * RPP;
            cp_async16(s + TILEB + r * RB + cc * 16,
                       Bh + (size_t)(bn + r) * K + k0 + cc * 8);
        }
        if (NT >= 2) {
#pragma unroll
            for (int i = 0; i < NPASS; i++) {
                int r = cr + i * RPP;
                cp_async16(s + 2 * TILEB + r * RB + cc * 16,
                           Al + (size_t)(bm + r) * K + k0 + cc * 8);
            }
        }
        CP_COMMIT();
    };

    // prologue: 2 stages in flight
    issue(0);
    issue(1);

    // ldmatrix lane addressing
    const int arow = lane & 15;
    const int akb = (lane >> 4) * 16;
    const int brow = (lane & 7) + ((lane >> 4) << 3);
    const int bkb = ((lane >> 3) & 1) * 16;

    for (int kt = 0; kt < ktpt; kt++) {
        CP_WAIT1();
        __syncthreads();
        uint32_t s0 = smem_u + (kt % NSTG) * STAGEB;

        if (NT == 1) {
            // 3-stage: issue immediately (slot kt+2 distinct from kt, kt+1)
            int nx = kt + 2;
            if (nx < ktpt) issue(nx);
            else CP_COMMIT();
        }

#pragma unroll
        for (int ks = 0; ks < NKS; ks++) {
            uint32_t a[4][4];
            uint32_t b[4][2];
#pragma unroll
            for (int mi = 0; mi < 4; mi++)
                ldsm_x4(a[mi][0], a[mi][1], a[mi][2], a[mi][3],
                        s0 + (uint32_t)(wm * 64 + mi * 16 + arow) * RB +
                            ks * 32 + akb);
#pragma unroll
            for (int nb = 0; nb < 2; nb++)
                ldsm_x4(b[2 * nb][0], b[2 * nb][1], b[2 * nb + 1][0],
                        b[2 * nb + 1][1],
                        s0 + TILEB +
                            (uint32_t)(wn * 32 + nb * 16 + brow) * RB +
                            ks * 32 + bkb);
            if (NT == 1) {
#pragma unroll
                for (int mi = 0; mi < 4; mi++)
#pragma unroll
                    for (int ni = 0; ni < 4; ni++)
                        mma16816(acc[mi][ni], a[mi], b[ni]);
            } else {  // NT == 2: batch loads, then 32 MMAs
                uint32_t al[4][4];
#pragma unroll
                for (int mi = 0; mi < 4; mi++)
                    ldsm_x4(al[mi][0], al[mi][1], al[mi][2], al[mi][3],
                            s0 + 2 * TILEB +
                                (uint32_t)(wm * 64 + mi * 16 + arow) * RB +
                                ks * 32 + akb);
#pragma unroll
                for (int mi = 0; mi < 4; mi++)
#pragma unroll
                    for (int ni = 0; ni < 4; ni++)
                        mma16816(acc[mi][ni], a[mi], b[ni]);
#pragma unroll
                for (int mi = 0; mi < 4; mi++)
#pragma unroll
                    for (int ni = 0; ni < 4; ni++)
                        mma16816(acc[mi][ni], al[mi], b[ni]);
            }
        }

        if (NT >= 2) {
            // 2-stage: finish reading before refilling this slot
            __syncthreads();
            int nx = kt + 2;
            if (nx < ktpt) issue(nx);
            else CP_COMMIT();
        }
    }
    CP_WAIT0();

    // ---------------- epilogue ----------------
    const int g = lane >> 2;
    const int tc = lane & 3;
    const int mirror = sym && ((int)blockIdx.x != (int)blockIdx.y);
    float k1 = 0.f;
    if (EPI == 2) k1 = g_coef[0] * s_f;

#pragma unroll
    for (int mi = 0; mi < 4; mi++) {
#pragma unroll
        for (int ni = 0; ni < 4; ni++) {
#pragma unroll
            for (int half = 0; half < 2; half++) {
                int row = bm + wm * 64 + mi * 16 + g + half * 8;
                int col = bn + wn * 32 + ni * 8 + tc * 2;
                float a0 = acc[mi][ni][half * 2 + 0];
                float a1 = acc[mi][ni][half * 2 + 1];
                size_t off = (size_t)row * N + col;
                if (EPI == 0) {
                    *(float2*)(Fout + off) = make_float2(s_f * a0, s_f * a1);
                } else {  // EPI == 2: Ph = fp16(k1 * acc)
                    uint32_t H = pack_h2(k1 * a0, k1 * a1);
                    *(uint32_t*)(Hout + off) = H;
                    if (mirror) {
                        *(unsigned short*)(Hout + (size_t)col * N + row) =
                            (unsigned short)(H & 0xffff);
                        *(unsigned short*)(Hout + (size_t)(col + 1) * N + row) =
                            (unsigned short)(H >> 16);
                    }
                }
            }
        }
    }
}

// ---------------------------------------------------------------------------
// Launch: retrieved = qh @ (256*alpha*G), G = A^T A  (G symmetric).
//   G via 2-term fp16 (Ah+Al).Ah^T, symmetrized by triangle+mirror
//   (measured increment: +1.19e-4 in quadrature, R10 vs R8).
// ---------------------------------------------------------------------------
extern "C" void kernel_launch(void* const* d_in, const int* in_sizes, int n_in,
                              void* d_out, int out_size) {
    const float* query = (const float*)d_in[0];      // (B, C)
    const float* A = (const float*)d_in[1];          // (K, C)
    const float* log_scale = (const float*)d_in[2];  // scalar
    float* out = (float*)d_out;                      // (B, C)

    __half *AhT, *AlT, *qh, *Ph;
    cudaGetSymbolAddress((void**)&AhT, g_AhT);
    cudaGetSymbolAddress((void**)&AlT, g_AlT);
    cudaGetSymbolAddress((void**)&qh, g_qh);
    cudaGetSymbolAddress((void**)&Ph, g_Ph);

    // GEMM1: NT2, KT64, RB144 -> 2 stages x 3 tiles x 18432 = 110592
    cudaFuncSetAttribute((const void*)mma_gemm_kernel<2, 2, 64, 144>,
                         cudaFuncAttributeMaxDynamicSharedMemorySize, 110592);
    // GEMM3: NT1, KT64, RB144 -> 3 stages x 2 tiles x 18432 = 110592
    cudaFuncSetAttribute((const void*)mma_gemm_kernel<0, 1, 64, 144>,
                         cudaFuncAttributeMaxDynamicSharedMemorySize, 110592);

    // 1) operand prep (fused ||A||^2 partials) + alpha
    split_transpose_kernel<<<dim3(C_DIM / 32, K_DIM / 32), 256>>>(A, AhT, AlT);
    finalize_alpha_kernel<<<1, 1024>>>(log_scale);
    convert_kernel<<<4096, 256>>>(query, qh, (B_DIM * C_DIM) / 4);

    // 2) Ph = fp16(8192*256*alpha*G), 2-term triangle + mirror
    mma_gemm_kernel<2, 2, 64, 144>
        <<<dim3(C_DIM / 128, C_DIM / 128), 256, 110592>>>(
        AhT, AlT, AhT, K_DIM, nullptr, Ph, C_DIM, 1, 1.0f / 4096.0f);

    // 3) out = qh @ Ph * 2^-13  (NT1, KT64: 64 MMAs/barrier)
    mma_gemm_kernel<0, 1, 64, 144>
        <<<dim3(C_DIM / 128, B_DIM / 128), 256, 110592>>>(
        qh, nullptr, Ph, C_DIM, out, nullptr, C_DIM, 0, 1.0f / 8192.0f);
}

// round 14
// speedup vs baseline: 3.0589x; 1.1989x over previous
#include <cuda_runtime.h>
#include <cuda_fp16.h>
#include <math.h>
#include <stdint.h>

#define K_DIM 4096
#define C_DIM 2048
#define B_DIM 8192

// ---------------------------------------------------------------------------
// Device scratch (no allocation allowed)
// ---------------------------------------------------------------------------
__device__ float g_partial[8192];    // one per split_transpose block
__device__ float g_coef[1];          // k1 = 8192*256*alpha

__device__ __half g_AhT[(size_t)C_DIM * K_DIM];  // fp16(64*A^T)  (C x K)
__device__ __half g_AlT[(size_t)C_DIM * K_DIM];  // fp16 residual
__device__ __half g_qh[(size_t)B_DIM * C_DIM];   // fp16(q)
__device__ __half g_Ph[(size_t)C_DIM * C_DIM];   // fp16(8192*P), P = 256*alpha*G

// ---------------------------------------------------------------------------
// Helpers (baseline sm_103 PTX only: cp.async + ldmatrix + mma.sync)
// ---------------------------------------------------------------------------
__device__ __forceinline__ uint32_t smem_to_u32(const void* smem_ptr) {
    uint32_t addr;
    asm("{ .reg .u64 tmp; cvta.to.shared.u64 tmp, %1; cvt.u32.u64 %0, tmp; }"
        : "=r"(addr) : "l"(smem_ptr));
    return addr;
}

__device__ __forceinline__ void cp_async16(uint32_t dst, const void* src) {
    asm volatile("cp.async.cg.shared.global [%0], [%1], 16;"
                 :: "r"(dst), "l"(src));
}
#define CP_COMMIT() asm volatile("cp.async.commit_group;" ::: "memory")
#define CP_WAIT1()  asm volatile("cp.async.wait_group 1;" ::: "memory")
#define CP_WAIT0()  asm volatile("cp.async.wait_group 0;" ::: "memory")

__device__ __forceinline__ void ldsm_x4(uint32_t& r0, uint32_t& r1,
                                        uint32_t& r2, uint32_t& r3,
                                        uint32_t addr) {
    asm volatile("ldmatrix.sync.aligned.m8n8.x4.shared.b16 {%0,%1,%2,%3}, [%4];"
                 : "=r"(r0), "=r"(r1), "=r"(r2), "=r"(r3) : "r"(addr));
}

__device__ __forceinline__ void mma16816(float* c, const uint32_t* a,
                                         const uint32_t* b) {
    asm volatile(
        "mma.sync.aligned.m16n8k16.row.col.f32.f16.f16.f32 "
        "{%0,%1,%2,%3}, {%4,%5,%6,%7}, {%8,%9}, {%0,%1,%2,%3};"
        : "+f"(c[0]), "+f"(c[1]), "+f"(c[2]), "+f"(c[3])
        : "r"(a[0]), "r"(a[1]), "r"(a[2]), "r"(a[3]), "r"(b[0]), "r"(b[1]));
}

__device__ __forceinline__ uint32_t pack_h2(float a, float b) {
    __half2 h = __floats2half2_rn(a, b);
    return *reinterpret_cast<uint32_t*>(&h);
}

// ---------------------------------------------------------------------------
// Operand prep: A (K x C fp32) -> A^T hi/lo fp16 (scaled by 64), C x K.
// Also accumulates per-block ||A||^2 partials (fro pass fused away).
// ---------------------------------------------------------------------------
__global__ __launch_bounds__(256) void split_transpose_kernel(
    const float* __restrict__ A, __half* __restrict__ hiT,
    __half* __restrict__ loT) {
    __shared__ float tile[32][33];
    __shared__ float red[256];
    int tx = threadIdx.x & 31, ty = threadIdx.x >> 5;
    int c0 = blockIdx.x * 32;
    int k0 = blockIdx.y * 32;
    float s = 0.f;
#pragma unroll
    for (int i = 0; i < 4; i++) {
        int r = ty + i * 8;
        float v = A[(size_t)(k0 + r) * C_DIM + c0 + tx];
        tile[r][tx] = v;
        s += v * v;
    }
    red[threadIdx.x] = s;
    __syncthreads();
    for (int o = 128; o > 0; o >>= 1) {
        if (threadIdx.x < o) red[threadIdx.x] += red[threadIdx.x + o];
        __syncthreads();
    }
    if (threadIdx.x == 0)
        g_partial[blockIdx.y * gridDim.x + blockIdx.x] = red[0];
#pragma unroll
    for (int i = 0; i < 4; i++) {
        int p = ty + i * 8;
        float v = tile[tx][p] * 64.0f;
        size_t o = (size_t)(c0 + p) * K_DIM + k0 + tx;
        __half h = __float2half_rn(v);
        hiT[o] = h;
        loT[o] = __float2half_rn(v - __half2float(h));  // subnormal-safe
    }
}

__global__ void finalize_alpha_kernel(const float* __restrict__ log_scale) {
    __shared__ float sh[1024];
    int t = threadIdx.x;
    float s = 0.f;
#pragma unroll
    for (int i = 0; i < 8; i++) s += g_partial[t + i * 1024];
    sh[t] = s;
    __syncthreads();
    for (int o = 512; o > 0; o >>= 1) {
        if (t < o) sh[t] += sh[t + o];
        __syncthreads();
    }
    if (t == 0) {
        float fro = sh[0];
        float a = fminf(expf(log_scale[0]), 5e-4f) / (fro + 1e-8f);
        g_coef[0] = 2097152.0f * a;          // 8192*256*alpha
    }
}

// q -> fp16(q)
__global__ __launch_bounds__(256) void convert_kernel(
    const float* __restrict__ X, __half* __restrict__ hi, int n4) {
    const float4* X4 = (const float4*)X;
    uint2* H = (uint2*)hi;
    for (int i = blockIdx.x * blockDim.x + threadIdx.x; i < n4;
         i += gridDim.x * blockDim.x) {
        float4 v = X4[i];
        uint2 h;
        h.x = pack_h2(v.x, v.y);
        h.y = pack_h2(v.z, v.w);
        H[i] = h;
    }
}

// ---------------------------------------------------------------------------
// GEMM1 (symmetric, 512 threads = 16 warps): Ph = fp16(k1*(Ah+Al).Ah^T/4096)
// Triangle grid has only 136 CTAs (< 148 SMs) -> 1 CTA/SM; 16 warps gives
// 4 warps/SMSP (the measured requirement to saturate HMMA throughput).
// Warp grid 2(M) x 8(N); warp tile 64x16; KT=64; 3-stage, 1 sync/kt;
// 64 MMAs per warp per barrier interval.
// ---------------------------------------------------------------------------
#define RB1 144
#define TILEB1 (128 * RB1)               // 18432
#define STAGEB1 (3 * TILEB1)             // 55296 (Ah, Bh, Al)
#define SMEM1 (3 * STAGEB1)              // 165888 (3 stages)

__global__ void __launch_bounds__(512, 1) gemm_sym_512(
    const __half* __restrict__ Ah, const __half* __restrict__ Al,
    const __half* __restrict__ Bh, int K, __half* __restrict__ Hout,
    int N, float s_f) {
    if ((int)blockIdx.x > (int)blockIdx.y) return;

    extern __shared__ char smem[];
    const uint32_t smem_u = smem_to_u32(smem);
    const int tid = threadIdx.x;
    const int lane = tid & 31;
    const int warp = tid >> 5;      // 0..15
    const int wm = warp & 1;        // 2 in M
    const int wn = warp >> 1;       // 8 in N
    const int bm = blockIdx.y * 128;
    const int bn = blockIdx.x * 128;
    const int ktpt = K / 64;

    float acc[4][2][4];
#pragma unroll
    for (int mi = 0; mi < 4; mi++)
#pragma unroll
        for (int ni = 0; ni < 2; ni++)
#pragma unroll
            for (int c = 0; c < 4; c++) acc[mi][ni][c] = 0.f;

    const int cr = tid >> 3;        // row 0..63 (2 passes -> 0..127)
    const int cc = tid & 7;         // 16B chunk 0..7

    auto issue = [&](int kt) {
        int k0 = kt * 64;
        uint32_t s = smem_u + (kt % 3) * STAGEB1;
#pragma unroll
        for (int i = 0; i < 2; i++) {
            int r = cr + i * 64;
            cp_async16(s + r * RB1 + cc * 16,
                       Ah + (size_t)(bm + r) * K + k0 + cc * 8);
        }
#pragma unroll
        for (int i = 0; i < 2; i++) {
            int r = cr + i * 64;
            cp_async16(s + TILEB1 + r * RB1 + cc * 16,
                       Bh + (size_t)(bn + r) * K + k0 + cc * 8);
        }
#pragma unroll
        for (int i = 0; i < 2; i++) {
            int r = cr + i * 64;
            cp_async16(s + 2 * TILEB1 + r * RB1 + cc * 16,
                       Al + (size_t)(bm + r) * K + k0 + cc * 8);
        }
        CP_COMMIT();
    };

    issue(0);
    issue(1);

    const int arow = lane & 15;
    const int akb = (lane >> 4) * 16;
    const int brow = (lane & 7) + ((lane >> 4) << 3);
    const int bkb = ((lane >> 3) & 1) * 16;

    for (int kt = 0; kt < ktpt; kt++) {
        CP_WAIT1();
        __syncthreads();
        uint32_t s0 = smem_u + (kt % 3) * STAGEB1;

        int nx = kt + 2;
        if (nx < ktpt) issue(nx);
        else CP_COMMIT();

#pragma unroll
        for (int ks = 0; ks < 4; ks++) {
            uint32_t a[4][4];
            uint32_t al[4][4];
            uint32_t b[2][2];
#pragma unroll
            for (int mi = 0; mi < 4; mi++)
                ldsm_x4(a[mi][0], a[mi][1], a[mi][2], a[mi][3],
                        s0 + (uint32_t)(wm * 64 + mi * 16 + arow) * RB1 +
                            ks * 32 + akb);
            ldsm_x4(b[0][0], b[0][1], b[1][0], b[1][1],
                    s0 + TILEB1 + (uint32_t)(wn * 16 + brow) * RB1 +
                        ks * 32 + bkb);
#pragma unroll
            for (int mi = 0; mi < 4; mi++)
                ldsm_x4(al[mi][0], al[mi][1], al[mi][2], al[mi][3],
                        s0 + 2 * TILEB1 +
                            (uint32_t)(wm * 64 + mi * 16 + arow) * RB1 +
                            ks * 32 + akb);
#pragma unroll
            for (int mi = 0; mi < 4; mi++)
#pragma unroll
                for (int ni = 0; ni < 2; ni++)
                    mma16816(acc[mi][ni], a[mi], b[ni]);
#pragma unroll
            for (int mi = 0; mi < 4; mi++)
#pragma unroll
                for (int ni = 0; ni < 2; ni++)
                    mma16816(acc[mi][ni], al[mi], b[ni]);
        }
    }
    CP_WAIT0();

    // epilogue: Ph = fp16(k1 * acc) + mirror
    const int g = lane >> 2;
    const int tc = lane & 3;
    const int mirror = (int)blockIdx.x != (int)blockIdx.y;
    const float k1 = g_coef[0] * s_f;

#pragma unroll
    for (int mi = 0; mi < 4; mi++) {
#pragma unroll
        for (int ni = 0; ni < 2; ni++) {
#pragma unroll
            for (int half = 0; half < 2; half++) {
                int row = bm + wm * 64 + mi * 16 + g + half * 8;
                int col = bn + wn * 16 + ni * 8 + tc * 2;
                float v0 = k1 * acc[mi][ni][half * 2 + 0];
                float v1 = k1 * acc[mi][ni][half * 2 + 1];
                uint32_t H = pack_h2(v0, v1);
                *(uint32_t*)(Hout + (size_t)row * N + col) = H;
                if (mirror) {
                    *(unsigned short*)(Hout + (size_t)col * N + row) =
                        (unsigned short)(H & 0xffff);
                    *(unsigned short*)(Hout + (size_t)(col + 1) * N + row) =
                        (unsigned short)(H >> 16);
                }
            }
        }
    }
}

// ---------------------------------------------------------------------------
// GEMM3 (proven config): out = qh @ Ph^T-sym * s_f
// NT1, KT64, RB144, 3-stage, 256 threads, 2 CTAs/SM. 318 TF/s measured.
// ---------------------------------------------------------------------------
#define RB3 144
#define TILEB3 (128 * RB3)
#define STAGEB3 (2 * TILEB3)             // Ah, Bh
#define SMEM3 (3 * STAGEB3)              // 110592

__global__ void __launch_bounds__(256, 2) gemm_qp_256(
    const __half* __restrict__ Ah, const __half* __restrict__ Bh,
    int K, float* __restrict__ Fout, int N, float s_f) {
    extern __shared__ char smem[];
    const uint32_t smem_u = smem_to_u32(smem);
    const int tid = threadIdx.x;
    const int lane = tid & 31;
    const int warp = tid >> 5;
    const int wm = warp & 1;
    const int wn = warp >> 1;
    const int bm = blockIdx.y * 128;
    const int bn = blockIdx.x * 128;
    const int ktpt = K / 64;

    float acc[4][4][4];
#pragma unroll
    for (int mi = 0; mi < 4; mi++)
#pragma unroll
        for (int ni = 0; ni < 4; ni++)
#pragma unroll
            for (int c = 0; c < 4; c++) acc[mi][ni][c] = 0.f;

    const int cr = tid >> 3;        // 0..31 (4 passes -> 0..127)
    const int cc = tid & 7;

    auto issue = [&](int kt) {
        int k0 = kt * 64;
        uint32_t s = smem_u + (kt % 3) * STAGEB3;
#pragma unroll
        for (int i = 0; i < 4; i++) {
            int r = cr + i * 32;
            cp_async16(s + r * RB3 + cc * 16,
                       Ah + (size_t)(bm + r) * K + k0 + cc * 8);
        }
#pragma unroll
        for (int i = 0; i < 4; i++) {
            int r = cr + i * 32;
            cp_async16(s + TILEB3 + r * RB3 + cc * 16,
                       Bh + (size_t)(bn + r) * K + k0 + cc * 8);
        }
        CP_COMMIT();
    };

    issue(0);
    issue(1);

    const int arow = lane & 15;
    const int akb = (lane >> 4) * 16;
    const int brow = (lane & 7) + ((lane >> 4) << 3);
    const int bkb = ((lane >> 3) & 1) * 16;

    for (int kt = 0; kt < ktpt; kt++) {
        CP_WAIT1();
        __syncthreads();
        uint32_t s0 = smem_u + (kt % 3) * STAGEB3;

        int nx = kt + 2;
        if (nx < ktpt) issue(nx);
        else CP_COMMIT();

#pragma unroll
        for (int ks = 0; ks < 4; ks++) {
            uint32_t a[4][4];
            uint32_t b[4][2];
#pragma unroll
            for (int mi = 0; mi < 4; mi++)
                ldsm_x4(a[mi][0], a[mi][1], a[mi][2], a[mi][3],
                        s0 + (uint32_t)(wm * 64 + mi * 16 + arow) * RB3 +
                            ks * 32 + akb);
#pragma unroll
            for (int nb = 0; nb < 2; nb++)
                ldsm_x4(b[2 * nb][0], b[2 * nb][1], b[2 * nb + 1][0],
                        b[2 * nb + 1][1],
                        s0 + TILEB3 +
                            (uint32_t)(wn * 32 + nb * 16 + brow) * RB3 +
                            ks * 32 + bkb);
#pragma unroll
            for (int mi = 0; mi < 4; mi++)
#pragma unroll
                for (int ni = 0; ni < 4; ni++)
                    mma16816(acc[mi][ni], a[mi], b[ni]);
        }
    }
    CP_WAIT0();

    const int g = lane >> 2;
    const int tc = lane & 3;
#pragma unroll
    for (int mi = 0; mi < 4; mi++) {
#pragma unroll
        for (int ni = 0; ni < 4; ni++) {
#pragma unroll
            for (int half = 0; half < 2; half++) {
                int row = bm + wm * 64 + mi * 16 + g + half * 8;
                int col = bn + wn * 32 + ni * 8 + tc * 2;
                size_t off = (size_t)row * N + col;
                *(float2*)(Fout + off) =
                    make_float2(s_f * acc[mi][ni][half * 2 + 0],
                                s_f * acc[mi][ni][half * 2 + 1]);
            }
        }
    }
}

// ---------------------------------------------------------------------------
// Launch: retrieved = qh @ (256*alpha*G), G = A^T A  (G symmetric).
// ---------------------------------------------------------------------------
extern "C" void kernel_launch(void* const* d_in, const int* in_sizes, int n_in,
                              void* d_out, int out_size) {
    const float* query = (const float*)d_in[0];      // (B, C)
    const float* A = (const float*)d_in[1];          // (K, C)
    const float* log_scale = (const float*)d_in[2];  // scalar
    float* out = (float*)d_out;                      // (B, C)

    __half *AhT, *AlT, *qh, *Ph;
    cudaGetSymbolAddress((void**)&AhT, g_AhT);
    cudaGetSymbolAddress((void**)&AlT, g_AlT);
    cudaGetSymbolAddress((void**)&qh, g_qh);
    cudaGetSymbolAddress((void**)&Ph, g_Ph);

    cudaFuncSetAttribute((const void*)gemm_sym_512,
                         cudaFuncAttributeMaxDynamicSharedMemorySize, SMEM1);
    cudaFuncSetAttribute((const void*)gemm_qp_256,
                         cudaFuncAttributeMaxDynamicSharedMemorySize, SMEM3);

    // 1) operand prep (fused ||A||^2 partials) + alpha
    split_transpose_kernel<<<dim3(C_DIM / 32, K_DIM / 32), 256>>>(A, AhT, AlT);
    finalize_alpha_kernel<<<1, 1024>>>(log_scale);
    convert_kernel<<<4096, 256>>>(query, qh, (B_DIM * C_DIM) / 4);

    // 2) Ph = fp16(8192*256*alpha*G), 2-term triangle + mirror, 16 warps/CTA
    gemm_sym_512<<<dim3(C_DIM / 128, C_DIM / 128), 512, SMEM1>>>(
        AhT, AlT, AhT, K_DIM, Ph, C_DIM, 1.0f / 4096.0f);

    // 3) out = qh @ Ph * 2^-13
    gemm_qp_256<<<dim3(C_DIM / 128, B_DIM / 128), 256, SMEM3>>>(
        qh, Ph, C_DIM, out, C_DIM, 1.0f / 8192.0f);
}

// round 15
// speedup vs baseline: 3.2281x; 1.0553x over previous
#include <cuda_runtime.h>
#include <cuda_fp16.h>
#include <math.h>
#include <stdint.h>

#define K_DIM 4096
#define C_DIM 2048
#define B_DIM 8192

// ---------------------------------------------------------------------------
// Device scratch (no allocation allowed)
// ---------------------------------------------------------------------------
__device__ float g_partial[8192];    // one per split_transpose block
__device__ float g_coef[1];          // k1 = 8192*256*alpha

__device__ __half g_AhT[(size_t)C_DIM * K_DIM];  // fp16(64*A^T)  (C x K)
__device__ __half g_AlT[(size_t)C_DIM * K_DIM];  // fp16 residual
__device__ __half g_qh[(size_t)B_DIM * C_DIM];   // fp16(q)
__device__ __half g_Ph[(size_t)C_DIM * C_DIM];   // fp16(8192*P), P = 256*alpha*G

// ---------------------------------------------------------------------------
// Helpers (baseline sm_103 PTX only: cp.async + ldmatrix + mma.sync)
// ---------------------------------------------------------------------------
__device__ __forceinline__ uint32_t smem_to_u32(const void* smem_ptr) {
    uint32_t addr;
    asm("{ .reg .u64 tmp; cvta.to.shared.u64 tmp, %1; cvt.u32.u64 %0, tmp; }"
        : "=r"(addr) : "l"(smem_ptr));
    return addr;
}

__device__ __forceinline__ void cp_async16(uint32_t dst, const void* src) {
    asm volatile("cp.async.cg.shared.global [%0], [%1], 16;"
                 :: "r"(dst), "l"(src));
}
#define CP_COMMIT() asm volatile("cp.async.commit_group;" ::: "memory")
#define CP_WAIT1()  asm volatile("cp.async.wait_group 1;" ::: "memory")
#define CP_WAIT0()  asm volatile("cp.async.wait_group 0;" ::: "memory")

__device__ __forceinline__ void ldsm_x4(uint32_t& r0, uint32_t& r1,
                                        uint32_t& r2, uint32_t& r3,
                                        uint32_t addr) {
    asm volatile("ldmatrix.sync.aligned.m8n8.x4.shared.b16 {%0,%1,%2,%3}, [%4];"
                 : "=r"(r0), "=r"(r1), "=r"(r2), "=r"(r3) : "r"(addr));
}

__device__ __forceinline__ void mma16816(float* c, const uint32_t* a,
                                         const uint32_t* b) {
    asm volatile(
        "mma.sync.aligned.m16n8k16.row.col.f32.f16.f16.f32 "
        "{%0,%1,%2,%3}, {%4,%5,%6,%7}, {%8,%9}, {%0,%1,%2,%3};"
        : "+f"(c[0]), "+f"(c[1]), "+f"(c[2]), "+f"(c[3])
        : "r"(a[0]), "r"(a[1]), "r"(a[2]), "r"(a[3]), "r"(b[0]), "r"(b[1]));
}

__device__ __forceinline__ uint32_t pack_h2(float a, float b) {
    __half2 h = __floats2half2_rn(a, b);
    return *reinterpret_cast<uint32_t*>(&h);
}

// ---------------------------------------------------------------------------
// Operand prep: A (K x C fp32) -> A^T hi/lo fp16 (scaled by 64), C x K.
// Also accumulates per-block ||A||^2 partials (fro pass fused away).
// ---------------------------------------------------------------------------
__global__ __launch_bounds__(256) void split_transpose_kernel(
    const float* __restrict__ A, __half* __restrict__ hiT,
    __half* __restrict__ loT) {
    __shared__ float tile[32][33];
    __shared__ float red[256];
    int tx = threadIdx.x & 31, ty = threadIdx.x >> 5;
    int c0 = blockIdx.x * 32;
    int k0 = blockIdx.y * 32;
    float s = 0.f;
#pragma unroll
    for (int i = 0; i < 4; i++) {
        int r = ty + i * 8;
        float v = A[(size_t)(k0 + r) * C_DIM + c0 + tx];
        tile[r][tx] = v;
        s += v * v;
    }
    red[threadIdx.x] = s;
    __syncthreads();
    for (int o = 128; o > 0; o >>= 1) {
        if (threadIdx.x < o) red[threadIdx.x] += red[threadIdx.x + o];
        __syncthreads();
    }
    if (threadIdx.x == 0)
        g_partial[blockIdx.y * gridDim.x + blockIdx.x] = red[0];
#pragma unroll
    for (int i = 0; i < 4; i++) {
        int p = ty + i * 8;
        float v = tile[tx][p] * 64.0f;
        size_t o = (size_t)(c0 + p) * K_DIM + k0 + tx;
        __half h = __float2half_rn(v);
        hiT[o] = h;
        loT[o] = __float2half_rn(v - __half2float(h));  // subnormal-safe
    }
}

__global__ void finalize_alpha_kernel(const float* __restrict__ log_scale) {
    __shared__ float sh[1024];
    int t = threadIdx.x;
    float s = 0.f;
#pragma unroll
    for (int i = 0; i < 8; i++) s += g_partial[t + i * 1024];
    sh[t] = s;
    __syncthreads();
    for (int o = 512; o > 0; o >>= 1) {
        if (t < o) sh[t] += sh[t + o];
        __syncthreads();
    }
    if (t == 0) {
        float fro = sh[0];
        float a = fminf(expf(log_scale[0]), 5e-4f) / (fro + 1e-8f);
        g_coef[0] = 2097152.0f * a;          // 8192*256*alpha
    }
}

// q -> fp16(q)
__global__ __launch_bounds__(256) void convert_kernel(
    const float* __restrict__ X, __half* __restrict__ hi, int n4) {
    const float4* X4 = (const float4*)X;
    uint2* H = (uint2*)hi;
    for (int i = blockIdx.x * blockDim.x + threadIdx.x; i < n4;
         i += gridDim.x * blockDim.x) {
        float4 v = X4[i];
        uint2 h;
        h.x = pack_h2(v.x, v.y);
        h.y = pack_h2(v.z, v.w);
        H[i] = h;
    }
}

// ---------------------------------------------------------------------------
// GEMM1 (symmetric, 512 threads = 16 warps): Ph = fp16(k1*(Ah+Al).Ah^T/4096)
// Warp grid 8(M) x 2(N), warp tile 16x64 -> per ks: a 1 + al 1 + b 4 = 6
// ldsm for 16 MMAs (192 B/MMA; relieves the measured 60% smem-read pressure
// of the previous 64x16 tile at 287 B/MMA). KT=64; 3-stage, 1 sync/kt.
// ---------------------------------------------------------------------------
#define RB1 144
#define TILEB1 (128 * RB1)               // 18432
#define STAGEB1 (3 * TILEB1)             // 55296 (Ah, Bh, Al)
#define SMEM1 (3 * STAGEB1)              // 165888 (3 stages)

__global__ void __launch_bounds__(512, 1) gemm_sym_512(
    const __half* __restrict__ Ah, const __half* __restrict__ Al,
    const __half* __restrict__ Bh, int K, __half* __restrict__ Hout,
    int N, float s_f) {
    if ((int)blockIdx.x > (int)blockIdx.y) return;

    extern __shared__ char smem[];
    const uint32_t smem_u = smem_to_u32(smem);
    const int tid = threadIdx.x;
    const int lane = tid & 31;
    const int warp = tid >> 5;      // 0..15
    const int wm = warp & 7;        // 8 in M
    const int wn = warp >> 3;       // 2 in N
    const int bm = blockIdx.y * 128;
    const int bn = blockIdx.x * 128;
    const int ktpt = K / 64;

    float acc[8][4];
#pragma unroll
    for (int ni = 0; ni < 8; ni++)
#pragma unroll
        for (int c = 0; c < 4; c++) acc[ni][c] = 0.f;

    const int cr = tid >> 3;        // row 0..63 (2 passes -> 0..127)
    const int cc = tid & 7;         // 16B chunk 0..7

    auto issue = [&](int kt) {
        int k0 = kt * 64;
        uint32_t s = smem_u + (kt % 3) * STAGEB1;
#pragma unroll
        for (int i = 0; i < 2; i++) {
            int r = cr + i * 64;
            cp_async16(s + r * RB1 + cc * 16,
                       Ah + (size_t)(bm + r) * K + k0 + cc * 8);
        }
#pragma unroll
        for (int i = 0; i < 2; i++) {
            int r = cr + i * 64;
            cp_async16(s + TILEB1 + r * RB1 + cc * 16,
                       Bh + (size_t)(bn + r) * K + k0 + cc * 8);
        }
#pragma unroll
        for (int i = 0; i < 2; i++) {
            int r = cr + i * 64;
            cp_async16(s + 2 * TILEB1 + r * RB1 + cc * 16,
                       Al + (size_t)(bm + r) * K + k0 + cc * 8);
        }
        CP_COMMIT();
    };

    issue(0);
    issue(1);

    const int arow = lane & 15;
    const int akb = (lane >> 4) * 16;
    const int brow = (lane & 7) + ((lane >> 4) << 3);
    const int bkb = ((lane >> 3) & 1) * 16;

    for (int kt = 0; kt < ktpt; kt++) {
        CP_WAIT1();
        __syncthreads();
        uint32_t s0 = smem_u + (kt % 3) * STAGEB1;

        int nx = kt + 2;
        if (nx < ktpt) issue(nx);
        else CP_COMMIT();

#pragma unroll
        for (int ks = 0; ks < 4; ks++) {
            uint32_t a[4], al[4];
            uint32_t b[8][2];
            ldsm_x4(a[0], a[1], a[2], a[3],
                    s0 + (uint32_t)(wm * 16 + arow) * RB1 + ks * 32 + akb);
            ldsm_x4(al[0], al[1], al[2], al[3],
                    s0 + 2 * TILEB1 + (uint32_t)(wm * 16 + arow) * RB1 +
                        ks * 32 + akb);
#pragma unroll
            for (int nb = 0; nb < 4; nb++)
                ldsm_x4(b[2 * nb][0], b[2 * nb][1], b[2 * nb + 1][0],
                        b[2 * nb + 1][1],
                        s0 + TILEB1 +
                            (uint32_t)(wn * 64 + nb * 16 + brow) * RB1 +
                            ks * 32 + bkb);
#pragma unroll
            for (int ni = 0; ni < 8; ni++)
                mma16816(acc[ni], a, b[ni]);
#pragma unroll
            for (int ni = 0; ni < 8; ni++)
                mma16816(acc[ni], al, b[ni]);
        }
    }
    CP_WAIT0();

    // epilogue: Ph = fp16(k1 * acc) + mirror
    const int g = lane >> 2;
    const int tc = lane & 3;
    const int mirror = (int)blockIdx.x != (int)blockIdx.y;
    const float k1 = g_coef[0] * s_f;

#pragma unroll
    for (int ni = 0; ni < 8; ni++) {
#pragma unroll
        for (int half = 0; half < 2; half++) {
            int row = bm + wm * 16 + g + half * 8;
            int col = bn + wn * 64 + ni * 8 + tc * 2;
            float v0 = k1 * acc[ni][half * 2 + 0];
            float v1 = k1 * acc[ni][half * 2 + 1];
            uint32_t H = pack_h2(v0, v1);
            *(uint32_t*)(Hout + (size_t)row * N + col) = H;
            if (mirror) {
                *(unsigned short*)(Hout + (size_t)col * N + row) =
                    (unsigned short)(H & 0xffff);
                *(unsigned short*)(Hout + (size_t)(col + 1) * N + row) =
                    (unsigned short)(H >> 16);
            }
        }
    }
}

// ---------------------------------------------------------------------------
// GEMM3 (proven config): out = qh @ Ph * s_f
// NT1, KT64, RB144, 3-stage, 256 threads, 2 CTAs/SM. ~410 TF/s measured.
// ---------------------------------------------------------------------------
#define RB3 144
#define TILEB3 (128 * RB3)
#define STAGEB3 (2 * TILEB3)             // Ah, Bh
#define SMEM3 (3 * STAGEB3)              // 110592

__global__ void __launch_bounds__(256, 2) gemm_qp_256(
    const __half* __restrict__ Ah, const __half* __restrict__ Bh,
    int K, float* __restrict__ Fout, int N, float s_f) {
    extern __shared__ char smem[];
    const uint32_t smem_u = smem_to_u32(smem);
    const int tid = threadIdx.x;
    const int lane = tid & 31;
    const int warp = tid >> 5;
    const int wm = warp & 1;
    const int wn = warp >> 1;
    const int bm = blockIdx.y * 128;
    const int bn = blockIdx.x * 128;
    const int ktpt = K / 64;

    float acc[4][4][4];
#pragma unroll
    for (int mi = 0; mi < 4; mi++)
#pragma unroll
        for (int ni = 0; ni < 4; ni++)
#pragma unroll
            for (int c = 0; c < 4; c++) acc[mi][ni][c] = 0.f;

    const int cr = tid >> 3;        // 0..31 (4 passes -> 0..127)
    const int cc = tid & 7;

    auto issue = [&](int kt) {
        int k0 = kt * 64;
        uint32_t s = smem_u + (kt % 3) * STAGEB3;
#pragma unroll
        for (int i = 0; i < 4; i++) {
            int r = cr + i * 32;
            cp_async16(s + r * RB3 + cc * 16,
                       Ah + (size_t)(bm + r) * K + k0 + cc * 8);
        }
#pragma unroll
        for (int i = 0; i < 4; i++) {
            int r = cr + i * 32;
            cp_async16(s + TILEB3 + r * RB3 + cc * 16,
                       Bh + (size_t)(bn + r) * K + k0 + cc * 8);
        }
        CP_COMMIT();
    };

    issue(0);
    issue(1);

    const int arow = lane & 15;
    const int akb = (lane >> 4) * 16;
    const int brow = (lane & 7) + ((lane >> 4) << 3);
    const int bkb = ((lane >> 3) & 1) * 16;

    for (int kt = 0; kt < ktpt; kt++) {
        CP_WAIT1();
        __syncthreads();
        uint32_t s0 = smem_u + (kt % 3) * STAGEB3;

        int nx = kt + 2;
        if (nx < ktpt) issue(nx);
        else CP_COMMIT();

#pragma unroll
        for (int ks = 0; ks < 4; ks++) {
            uint32_t a[4][4];
            uint32_t b[4][2];
#pragma unroll
            for (int mi = 0; mi < 4; mi++)
                ldsm_x4(a[mi][0], a[mi][1], a[mi][2], a[mi][3],
                        s0 + (uint32_t)(wm * 64 + mi * 16 + arow) * RB3 +
                            ks * 32 + akb);
#pragma unroll
            for (int nb = 0; nb < 2; nb++)
                ldsm_x4(b[2 * nb][0], b[2 * nb][1], b[2 * nb + 1][0],
                        b[2 * nb + 1][1],
                        s0 + TILEB3 +
                            (uint32_t)(wn * 32 + nb * 16 + brow) * RB3 +
                            ks * 32 + bkb);
#pragma unroll
            for (int mi = 0; mi < 4; mi++)
#pragma unroll
                for (int ni = 0; ni < 4; ni++)
                    mma16816(acc[mi][ni], a[mi], b[ni]);
        }
    }
    CP_WAIT0();

    const int g = lane >> 2;
    const int tc = lane & 3;
#pragma unroll
    for (int mi = 0; mi < 4; mi++) {
#pragma unroll
        for (int ni = 0; ni < 4; ni++) {
#pragma unroll
            for (int half = 0; half < 2; half++) {
                int row = bm + wm * 64 + mi * 16 + g + half * 8;
                int col = bn + wn * 32 + ni * 8 + tc * 2;
                size_t off = (size_t)row * N + col;
                *(float2*)(Fout + off) =
                    make_float2(s_f * acc[mi][ni][half * 2 + 0],
                                s_f * acc[mi][ni][half * 2 + 1]);
            }
        }
    }
}

// ---------------------------------------------------------------------------
// Launch: retrieved = qh @ (256*alpha*G), G = A^T A  (G symmetric).
// ---------------------------------------------------------------------------
extern "C" void kernel_launch(void* const* d_in, const int* in_sizes, int n_in,
                              void* d_out, int out_size) {
    const float* query = (const float*)d_in[0];      // (B, C)
    const float* A = (const float*)d_in[1];          // (K, C)
    const float* log_scale = (const float*)d_in[2];  // scalar
    float* out = (float*)d_out;                      // (B, C)

    __half *AhT, *AlT, *qh, *Ph;
    cudaGetSymbolAddress((void**)&AhT, g_AhT);
    cudaGetSymbolAddress((void**)&AlT, g_AlT);
    cudaGetSymbolAddress((void**)&qh, g_qh);
    cudaGetSymbolAddress((void**)&Ph, g_Ph);

    cudaFuncSetAttribute((const void*)gemm_sym_512,
                         cudaFuncAttributeMaxDynamicSharedMemorySize, SMEM1);
    cudaFuncSetAttribute((const void*)gemm_qp_256,
                         cudaFuncAttributeMaxDynamicSharedMemorySize, SMEM3);

    // 1) operand prep (fused ||A||^2 partials) + alpha
    split_transpose_kernel<<<dim3(C_DIM / 32, K_DIM / 32), 256>>>(A, AhT, AlT);
    finalize_alpha_kernel<<<1, 1024>>>(log_scale);
    convert_kernel<<<4096, 256>>>(query, qh, (B_DIM * C_DIM) / 4);

    // 2) Ph = fp16(8192*256*alpha*G), 2-term triangle + mirror, 16 warps/CTA
    gemm_sym_512<<<dim3(C_DIM / 128, C_DIM / 128), 512, SMEM1>>>(
        AhT, AlT, AhT, K_DIM, Ph, C_DIM, 1.0f / 4096.0f);

    // 3) out = qh @ Ph * 2^-13
    gemm_qp_256<<<dim3(C_DIM / 128, B_DIM / 128), 256, SMEM3>>>(
        qh, Ph, C_DIM, out, C_DIM, 1.0f / 8192.0f);
}

// round 16
// speedup vs baseline: 3.5536x; 1.1008x over previous
#include <cuda_runtime.h>
#include <cuda_fp16.h>
#include <math.h>
#include <stdint.h>

#define K_DIM 4096
#define C_DIM 2048
#define B_DIM 8192

// ---------------------------------------------------------------------------
// Device scratch (no allocation allowed)
// ---------------------------------------------------------------------------
__device__ float g_partial[8192];    // one per transpose block
__device__ float g_coef[1];          // k1 = 8192*256*alpha

__device__ __half g_AhT[(size_t)C_DIM * K_DIM];  // fp16(64*A^T)  (C x K)
__device__ __half g_qh[(size_t)B_DIM * C_DIM];   // fp16(q)
__device__ __half g_Ph[(size_t)C_DIM * C_DIM];   // fp16(8192*P), P = 256*alpha*G

// ---------------------------------------------------------------------------
// Helpers (baseline sm_103 PTX only: cp.async + ldmatrix + mma.sync)
// ---------------------------------------------------------------------------
__device__ __forceinline__ uint32_t smem_to_u32(const void* smem_ptr) {
    uint32_t addr;
    asm("{ .reg .u64 tmp; cvta.to.shared.u64 tmp, %1; cvt.u32.u64 %0, tmp; }"
        : "=r"(addr) : "l"(smem_ptr));
    return addr;
}

__device__ __forceinline__ void cp_async16(uint32_t dst, const void* src) {
    asm volatile("cp.async.cg.shared.global [%0], [%1], 16;"
                 :: "r"(dst), "l"(src));
}
#define CP_COMMIT() asm volatile("cp.async.commit_group;" ::: "memory")
#define CP_WAIT1()  asm volatile("cp.async.wait_group 1;" ::: "memory")
#define CP_WAIT0()  asm volatile("cp.async.wait_group 0;" ::: "memory")

__device__ __forceinline__ void ldsm_x4(uint32_t& r0, uint32_t& r1,
                                        uint32_t& r2, uint32_t& r3,
                                        uint32_t addr) {
    asm volatile("ldmatrix.sync.aligned.m8n8.x4.shared.b16 {%0,%1,%2,%3}, [%4];"
                 : "=r"(r0), "=r"(r1), "=r"(r2), "=r"(r3) : "r"(addr));
}

__device__ __forceinline__ void mma16816(float* c, const uint32_t* a,
                                         const uint32_t* b) {
    asm volatile(
        "mma.sync.aligned.m16n8k16.row.col.f32.f16.f16.f32 "
        "{%0,%1,%2,%3}, {%4,%5,%6,%7}, {%8,%9}, {%0,%1,%2,%3};"
        : "+f"(c[0]), "+f"(c[1]), "+f"(c[2]), "+f"(c[3])
        : "r"(a[0]), "r"(a[1]), "r"(a[2]), "r"(a[3]), "r"(b[0]), "r"(b[1]));
}

__device__ __forceinline__ uint32_t pack_h2(float a, float b) {
    __half2 h = __floats2half2_rn(a, b);
    return *reinterpret_cast<uint32_t*>(&h);
}

// ---------------------------------------------------------------------------
// Operand prep: A (K x C fp32) -> A^T fp16 (scaled by 64), C x K.
// Also accumulates per-block ||A||^2 partials (fro pass fused away).
// ---------------------------------------------------------------------------
__global__ __launch_bounds__(256) void convert_transpose_kernel(
    const float* __restrict__ A, __half* __restrict__ hiT) {
    __shared__ float tile[32][33];
    __shared__ float red[256];
    int tx = threadIdx.x & 31, ty = threadIdx.x >> 5;
    int c0 = blockIdx.x * 32;
    int k0 = blockIdx.y * 32;
    float s = 0.f;
#pragma unroll
    for (int i = 0; i < 4; i++) {
        int r = ty + i * 8;
        float v = A[(size_t)(k0 + r) * C_DIM + c0 + tx];
        tile[r][tx] = v;
        s += v * v;
    }
    red[threadIdx.x] = s;
    __syncthreads();
    for (int o = 128; o > 0; o >>= 1) {
        if (threadIdx.x < o) red[threadIdx.x] += red[threadIdx.x + o];
        __syncthreads();
    }
    if (threadIdx.x == 0)
        g_partial[blockIdx.y * gridDim.x + blockIdx.x] = red[0];
#pragma unroll
    for (int i = 0; i < 4; i++) {
        int p = ty + i * 8;
        float v = tile[tx][p] * 64.0f;
        hiT[(size_t)(c0 + p) * K_DIM + k0 + tx] = __float2half_rn(v);
    }
}

__global__ void finalize_alpha_kernel(const float* __restrict__ log_scale) {
    __shared__ float sh[1024];
    int t = threadIdx.x;
    float s = 0.f;
#pragma unroll
    for (int i = 0; i < 8; i++) s += g_partial[t + i * 1024];
    sh[t] = s;
    __syncthreads();
    for (int o = 512; o > 0; o >>= 1) {
        if (t < o) sh[t] += sh[t + o];
        __syncthreads();
    }
    if (t == 0) {
        float fro = sh[0];
        float a = fminf(expf(log_scale[0]), 5e-4f) / (fro + 1e-8f);
        g_coef[0] = 2097152.0f * a;          // 8192*256*alpha
    }
}

// q -> fp16(q)
__global__ __launch_bounds__(256) void convert_kernel(
    const float* __restrict__ X, __half* __restrict__ hi, int n4) {
    const float4* X4 = (const float4*)X;
    uint2* H = (uint2*)hi;
    for (int i = blockIdx.x * blockDim.x + threadIdx.x; i < n4;
         i += gridDim.x * blockDim.x) {
        float4 v = X4[i];
        uint2 h;
        h.x = pack_h2(v.x, v.y);
        h.y = pack_h2(v.z, v.w);
        H[i] = h;
    }
}

// ---------------------------------------------------------------------------
// GEMM1 (symmetric SYRK, 512 threads = 16 warps): Ph = fp16(k1*Ah.Ah^T/4096)
// Warp grid 8(M) x 2(N), warp tile 16x64; KT=64; 3-stage, 1 sync/kt.
// 4 warps/SMSP x 32 MMAs/kt = 128 MMAs per SMSP per barrier (saturation
// threshold per the R7/R12/R15 density model). Triangle grid + mirror.
// ---------------------------------------------------------------------------
#define RB1 144
#define TILEB1 (128 * RB1)               // 18432
#define STAGEB1 (2 * TILEB1)             // 36864 (Ah, Bh)
#define SMEM1 (3 * STAGEB1)              // 110592 (3 stages)

__global__ void __launch_bounds__(512, 1) gemm_sym_512(
    const __half* __restrict__ Ah, const __half* __restrict__ Bh,
    int K, __half* __restrict__ Hout, int N, float s_f) {
    if ((int)blockIdx.x > (int)blockIdx.y) return;

    extern __shared__ char smem[];
    const uint32_t smem_u = smem_to_u32(smem);
    const int tid = threadIdx.x;
    const int lane = tid & 31;
    const int warp = tid >> 5;      // 0..15
    const int wm = warp & 7;        // 8 in M
    const int wn = warp >> 3;       // 2 in N
    const int bm = blockIdx.y * 128;
    const int bn = blockIdx.x * 128;
    const int ktpt = K / 64;

    float acc[8][4];
#pragma unroll
    for (int ni = 0; ni < 8; ni++)
#pragma unroll
        for (int c = 0; c < 4; c++) acc[ni][c] = 0.f;

    const int cr = tid >> 3;        // row 0..63 (2 passes -> 0..127)
    const int cc = tid & 7;         // 16B chunk 0..7

    auto issue = [&](int kt) {
        int k0 = kt * 64;
        uint32_t s = smem_u + (kt % 3) * STAGEB1;
#pragma unroll
        for (int i = 0; i < 2; i++) {
            int r = cr + i * 64;
            cp_async16(s + r * RB1 + cc * 16,
                       Ah + (size_t)(bm + r) * K + k0 + cc * 8);
        }
#pragma unroll
        for (int i = 0; i < 2; i++) {
            int r = cr + i * 64;
            cp_async16(s + TILEB1 + r * RB1 + cc * 16,
                       Bh + (size_t)(bn + r) * K + k0 + cc * 8);
        }
        CP_COMMIT();
    };

    issue(0);
    issue(1);

    const int arow = lane & 15;
    const int akb = (lane >> 4) * 16;
    const int brow = (lane & 7) + ((lane >> 4) << 3);
    const int bkb = ((lane >> 3) & 1) * 16;

    for (int kt = 0; kt < ktpt; kt++) {
        CP_WAIT1();
        __syncthreads();
        uint32_t s0 = smem_u + (kt % 3) * STAGEB1;

        int nx = kt + 2;
        if (nx < ktpt) issue(nx);
        else CP_COMMIT();

#pragma unroll
        for (int ks = 0; ks < 4; ks++) {
            uint32_t a[4];
            uint32_t b[8][2];
            ldsm_x4(a[0], a[1], a[2], a[3],
                    s0 + (uint32_t)(wm * 16 + arow) * RB1 + ks * 32 + akb);
#pragma unroll
            for (int nb = 0; nb < 4; nb++)
                ldsm_x4(b[2 * nb][0], b[2 * nb][1], b[2 * nb + 1][0],
                        b[2 * nb + 1][1],
                        s0 + TILEB1 +
                            (uint32_t)(wn * 64 + nb * 16 + brow) * RB1 +
                            ks * 32 + bkb);
#pragma unroll
            for (int ni = 0; ni < 8; ni++)
                mma16816(acc[ni], a, b[ni]);
        }
    }
    CP_WAIT0();

    // epilogue: Ph = fp16(k1 * acc) + mirror
    const int g = lane >> 2;
    const int tc = lane & 3;
    const int mirror = (int)blockIdx.x != (int)blockIdx.y;
    const float k1 = g_coef[0] * s_f;

#pragma unroll
    for (int ni = 0; ni < 8; ni++) {
#pragma unroll
        for (int half = 0; half < 2; half++) {
            int row = bm + wm * 16 + g + half * 8;
            int col = bn + wn * 64 + ni * 8 + tc * 2;
            float v0 = k1 * acc[ni][half * 2 + 0];
            float v1 = k1 * acc[ni][half * 2 + 1];
            uint32_t H = pack_h2(v0, v1);
            *(uint32_t*)(Hout + (size_t)row * N + col) = H;
            if (mirror) {
                *(unsigned short*)(Hout + (size_t)col * N + row) =
                    (unsigned short)(H & 0xffff);
                *(unsigned short*)(Hout + (size_t)(col + 1) * N + row) =
                    (unsigned short)(H >> 16);
            }
        }
    }
}

// ---------------------------------------------------------------------------
// GEMM3 (proven config): out = qh @ Ph * s_f
// NT1, KT64, RB144, 3-stage, 256 threads, 2 CTAs/SM. ~430 TF/s measured.
// ---------------------------------------------------------------------------
#define RB3 144
#define TILEB3 (128 * RB3)
#define STAGEB3 (2 * TILEB3)             // Ah, Bh
#define SMEM3 (3 * STAGEB3)              // 110592

__global__ void __launch_bounds__(256, 2) gemm_qp_256(
    const __half* __restrict__ Ah, const __half* __restrict__ Bh,
    int K, float* __restrict__ Fout, int N, float s_f) {
    extern __shared__ char smem[];
    const uint32_t smem_u = smem_to_u32(smem);
    const int tid = threadIdx.x;
    const int lane = tid & 31;
    const int warp = tid >> 5;
    const int wm = warp & 1;
    const int wn = warp >> 1;
    const int bm = blockIdx.y * 128;
    const int bn = blockIdx.x * 128;
    const int ktpt = K / 64;

    float acc[4][4][4];
#pragma unroll
    for (int mi = 0; mi < 4; mi++)
#pragma unroll
        for (int ni = 0; ni < 4; ni++)
#pragma unroll
            for (int c = 0; c < 4; c++) acc[mi][ni][c] = 0.f;

    const int cr = tid >> 3;        // 0..31 (4 passes -> 0..127)
    const int cc = tid & 7;

    auto issue = [&](int kt) {
        int k0 = kt * 64;
        uint32_t s = smem_u + (kt % 3) * STAGEB3;
#pragma unroll
        for (int i = 0; i < 4; i++) {
            int r = cr + i * 32;
            cp_async16(s + r * RB3 + cc * 16,
                       Ah + (size_t)(bm + r) * K + k0 + cc * 8);
        }
#pragma unroll
        for (int i = 0; i < 4; i++) {
            int r = cr + i * 32;
            cp_async16(s + TILEB3 + r * RB3 + cc * 16,
                       Bh + (size_t)(bn + r) * K + k0 + cc * 8);
        }
        CP_COMMIT();
    };

    issue(0);
    issue(1);

    const int arow = lane & 15;
    const int akb = (lane >> 4) * 16;
    const int brow = (lane & 7) + ((lane >> 4) << 3);
    const int bkb = ((lane >> 3) & 1) * 16;

    for (int kt = 0; kt < ktpt; kt++) {
        CP_WAIT1();
        __syncthreads();
        uint32_t s0 = smem_u + (kt % 3) * STAGEB3;

        int nx = kt + 2;
        if (nx < ktpt) issue(nx);
        else CP_COMMIT();

#pragma unroll
        for (int ks = 0; ks < 4; ks++) {
            uint32_t a[4][4];
            uint32_t b[4][2];
#pragma unroll
            for (int mi = 0; mi < 4; mi++)
                ldsm_x4(a[mi][0], a[mi][1], a[mi][2], a[mi][3],
                        s0 + (uint32_t)(wm * 64 + mi * 16 + arow) * RB3 +
                            ks * 32 + akb);
#pragma unroll
            for (int nb = 0; nb < 2; nb++)
                ldsm_x4(b[2 * nb][0], b[2 * nb][1], b[2 * nb + 1][0],
                        b[2 * nb + 1][1],
                        s0 + TILEB3 +
                            (uint32_t)(wn * 32 + nb * 16 + brow) * RB3 +
                            ks * 32 + bkb);
#pragma unroll
            for (int mi = 0; mi < 4; mi++)
#pragma unroll
                for (int ni = 0; ni < 4; ni++)
                    mma16816(acc[mi][ni], a[mi], b[ni]);
        }
    }
    CP_WAIT0();

    const int g = lane >> 2;
    const int tc = lane & 3;
#pragma unroll
    for (int mi = 0; mi < 4; mi++) {
#pragma unroll
        for (int ni = 0; ni < 4; ni++) {
#pragma unroll
            for (int half = 0; half < 2; half++) {
                int row = bm + wm * 64 + mi * 16 + g + half * 8;
                int col = bn + wn * 32 + ni * 8 + tc * 2;
                size_t off = (size_t)row * N + col;
                *(float2*)(Fout + off) =
                    make_float2(s_f * acc[mi][ni][half * 2 + 0],
                                s_f * acc[mi][ni][half * 2 + 1]);
            }
        }
    }
}

// ---------------------------------------------------------------------------
// Launch: retrieved = qh @ (256*alpha*G), G ~= Ah.Ah^T (1-term SYRK).
// ---------------------------------------------------------------------------
extern "C" void kernel_launch(void* const* d_in, const int* in_sizes, int n_in,
                              void* d_out, int out_size) {
    const float* query = (const float*)d_in[0];      // (B, C)
    const float* A = (const float*)d_in[1];          // (K, C)
    const float* log_scale = (const float*)d_in[2];  // scalar
    float* out = (float*)d_out;                      // (B, C)

    __half *AhT, *qh, *Ph;
    cudaGetSymbolAddress((void**)&AhT, g_AhT);
    cudaGetSymbolAddress((void**)&qh, g_qh);
    cudaGetSymbolAddress((void**)&Ph, g_Ph);

    cudaFuncSetAttribute((const void*)gemm_sym_512,
                         cudaFuncAttributeMaxDynamicSharedMemorySize, SMEM1);
    cudaFuncSetAttribute((const void*)gemm_qp_256,
                         cudaFuncAttributeMaxDynamicSharedMemorySize, SMEM3);

    // 1) operand prep (fused ||A||^2 partials) + alpha
    convert_transpose_kernel<<<dim3(C_DIM / 32, K_DIM / 32), 256>>>(A, AhT);
    finalize_alpha_kernel<<<1, 1024>>>(log_scale);
    convert_kernel<<<4096, 256>>>(query, qh, (B_DIM * C_DIM) / 4);

    // 2) Ph = fp16(8192*256*alpha*G), 1-term SYRK, triangle + mirror
    gemm_sym_512<<<dim3(C_DIM / 128, C_DIM / 128), 512, SMEM1>>>(
        AhT, AhT, K_DIM, Ph, C_DIM, 1.0f / 4096.0f);

    // 3) out = qh @ Ph * 2^-13
    gemm_qp_256<<<dim3(C_DIM / 128, B_DIM / 128), 256, SMEM3>>>(
        qh, Ph, C_DIM, out, C_DIM, 1.0f / 8192.0f);
}

// round 17
// speedup vs baseline: 3.7542x; 1.0565x over previous
#include <cuda_runtime.h>
#include <cuda_fp16.h>
#include <math.h>
#include <stdint.h>

#define K_DIM 4096
#define C_DIM 2048
#define B_DIM 8192

// ---------------------------------------------------------------------------
// Device scratch (no allocation allowed)
// ---------------------------------------------------------------------------
__device__ float g_partial[8192];    // one per transpose block
__device__ float g_coef[1];          // k1 = 8192*256*alpha

__device__ __half g_AhT[(size_t)C_DIM * K_DIM];  // fp16(64*A^T)  (C x K)
__device__ __half g_qh[(size_t)B_DIM * C_DIM];   // fp16(q)
__device__ __half g_Ph[(size_t)C_DIM * C_DIM];   // fp16(8192*P), P = 256*alpha*G

// ---------------------------------------------------------------------------
// Helpers (baseline sm_103 PTX only: cp.async + ldmatrix + mma.sync)
// ---------------------------------------------------------------------------
__device__ __forceinline__ uint32_t smem_to_u32(const void* smem_ptr) {
    uint32_t addr;
    asm("{ .reg .u64 tmp; cvta.to.shared.u64 tmp, %1; cvt.u32.u64 %0, tmp; }"
        : "=r"(addr) : "l"(smem_ptr));
    return addr;
}

__device__ __forceinline__ void cp_async16(uint32_t dst, const void* src) {
    asm volatile("cp.async.cg.shared.global [%0], [%1], 16;"
                 :: "r"(dst), "l"(src));
}
#define CP_COMMIT() asm volatile("cp.async.commit_group;" ::: "memory")
#define CP_WAIT1()  asm volatile("cp.async.wait_group 1;" ::: "memory")
#define CP_WAIT0()  asm volatile("cp.async.wait_group 0;" ::: "memory")

__device__ __forceinline__ void ldsm_x4(uint32_t& r0, uint32_t& r1,
                                        uint32_t& r2, uint32_t& r3,
                                        uint32_t addr) {
    asm volatile("ldmatrix.sync.aligned.m8n8.x4.shared.b16 {%0,%1,%2,%3}, [%4];"
                 : "=r"(r0), "=r"(r1), "=r"(r2), "=r"(r3) : "r"(addr));
}

__device__ __forceinline__ void mma16816(float* c, const uint32_t* a,
                                         const uint32_t* b) {
    asm volatile(
        "mma.sync.aligned.m16n8k16.row.col.f32.f16.f16.f32 "
        "{%0,%1,%2,%3}, {%4,%5,%6,%7}, {%8,%9}, {%0,%1,%2,%3};"
        : "+f"(c[0]), "+f"(c[1]), "+f"(c[2]), "+f"(c[3])
        : "r"(a[0]), "r"(a[1]), "r"(a[2]), "r"(a[3]), "r"(b[0]), "r"(b[1]));
}

__device__ __forceinline__ uint32_t pack_h2(float a, float b) {
    __half2 h = __floats2half2_rn(a, b);
    return *reinterpret_cast<uint32_t*>(&h);
}

// ---------------------------------------------------------------------------
// Operand prep: A (K x C fp32) -> A^T fp16 (scaled by 64), C x K.
// Also accumulates per-block ||A||^2 partials (fro pass fused away).
// ---------------------------------------------------------------------------
__global__ __launch_bounds__(256) void convert_transpose_kernel(
    const float* __restrict__ A, __half* __restrict__ hiT) {
    __shared__ float tile[32][33];
    __shared__ float red[256];
    int tx = threadIdx.x & 31, ty = threadIdx.x >> 5;
    int c0 = blockIdx.x * 32;
    int k0 = blockIdx.y * 32;
    float s = 0.f;
#pragma unroll
    for (int i = 0; i < 4; i++) {
        int r = ty + i * 8;
        float v = A[(size_t)(k0 + r) * C_DIM + c0 + tx];
        tile[r][tx] = v;
        s += v * v;
    }
    red[threadIdx.x] = s;
    __syncthreads();
    for (int o = 128; o > 0; o >>= 1) {
        if (threadIdx.x < o) red[threadIdx.x] += red[threadIdx.x + o];
        __syncthreads();
    }
    if (threadIdx.x == 0)
        g_partial[blockIdx.y * gridDim.x + blockIdx.x] = red[0];
#pragma unroll
    for (int i = 0; i < 4; i++) {
        int p = ty + i * 8;
        float v = tile[tx][p] * 64.0f;
        hiT[(size_t)(c0 + p) * K_DIM + k0 + tx] = __float2half_rn(v);
    }
}

__global__ void finalize_alpha_kernel(const float* __restrict__ log_scale) {
    __shared__ float sh[1024];
    int t = threadIdx.x;
    float s = 0.f;
#pragma unroll
    for (int i = 0; i < 8; i++) s += g_partial[t + i * 1024];
    sh[t] = s;
    __syncthreads();
    for (int o = 512; o > 0; o >>= 1) {
        if (t < o) sh[t] += sh[t + o];
        __syncthreads();
    }
    if (t == 0) {
        float fro = sh[0];
        float a = fminf(expf(log_scale[0]), 5e-4f) / (fro + 1e-8f);
        g_coef[0] = 2097152.0f * a;          // 8192*256*alpha
    }
}

// q -> fp16(q)
__global__ __launch_bounds__(256) void convert_kernel(
    const float* __restrict__ X, __half* __restrict__ hi, int n4) {
    const float4* X4 = (const float4*)X;
    uint2* H = (uint2*)hi;
    for (int i = blockIdx.x * blockDim.x + threadIdx.x; i < n4;
         i += gridDim.x * blockDim.x) {
        float4 v = X4[i];
        uint2 h;
        h.x = pack_h2(v.x, v.y);
        h.y = pack_h2(v.z, v.w);
        H[i] = h;
    }
}

// ---------------------------------------------------------------------------
// GEMM1 (symmetric SYRK, 512 threads, split-K): Ph = fp16(k1*Ah.Ah^T/4096)
// Warp grid 2(M) x 4(N) x 2(K); warp tile 64x32; each K-half warp handles
// 2 of the 4 ks slices -> per ks: 4 a-ldsm + 2 b-ldsm for 16 MMAs
// (192 B/MMA, the proven-efficient smem ratio; fixes the measured 320 B/MMA
// crossbar bottleneck of the 16x64 tile). Density: 4 warps/SMSP x 32 MMAs/kt
// = 128 per SMSP-barrier (saturation threshold). Epilogue: kw=1 warps dump
// acc to (dead) pipeline smem; kw=0 warps reduce + write Ph + mirror.
// ---------------------------------------------------------------------------
#define RB1 144
#define TILEB1 (128 * RB1)               // 18432
#define STAGEB1 (2 * TILEB1)             // 36864 (Ah, Bh)
#define SMEM1 (3 * STAGEB1)              // 110592 (3 stages)

__global__ void __launch_bounds__(512, 1) gemm_sym_512(
    const __half* __restrict__ Ah, const __half* __restrict__ Bh,
    int K, __half* __restrict__ Hout, int N, float s_f) {
    if ((int)blockIdx.x > (int)blockIdx.y) return;

    extern __shared__ char smem[];
    const uint32_t smem_u = smem_to_u32(smem);
    const int tid = threadIdx.x;
    const int lane = tid & 31;
    const int warp = tid >> 5;      // 0..15
    const int kw = warp & 1;        // 2 in K
    const int w2 = warp >> 1;       // 0..7
    const int wm = w2 & 1;          // 2 in M (64 rows)
    const int wn = w2 >> 1;         // 4 in N (32 cols)
    const int bm = blockIdx.y * 128;
    const int bn = blockIdx.x * 128;
    const int ktpt = K / 64;

    float acc[4][4][4];
#pragma unroll
    for (int mi = 0; mi < 4; mi++)
#pragma unroll
        for (int ni = 0; ni < 4; ni++)
#pragma unroll
            for (int c = 0; c < 4; c++) acc[mi][ni][c] = 0.f;

    const int cr = tid >> 3;        // row 0..63 (2 passes -> 0..127)
    const int cc = tid & 7;         // 16B chunk 0..7

    auto issue = [&](int kt) {
        int k0 = kt * 64;
        uint32_t s = smem_u + (kt % 3) * STAGEB1;
#pragma unroll
        for (int i = 0; i < 2; i++) {
            int r = cr + i * 64;
            cp_async16(s + r * RB1 + cc * 16,
                       Ah + (size_t)(bm + r) * K + k0 + cc * 8);
        }
#pragma unroll
        for (int i = 0; i < 2; i++) {
            int r = cr + i * 64;
            cp_async16(s + TILEB1 + r * RB1 + cc * 16,
                       Bh + (size_t)(bn + r) * K + k0 + cc * 8);
        }
        CP_COMMIT();
    };

    issue(0);
    issue(1);

    const int arow = lane & 15;
    const int akb = (lane >> 4) * 16;
    const int brow = (lane & 7) + ((lane >> 4) << 3);
    const int bkb = ((lane >> 3) & 1) * 16;

    for (int kt = 0; kt < ktpt; kt++) {
        CP_WAIT1();
        __syncthreads();
        uint32_t s0 = smem_u + (kt % 3) * STAGEB1;

        int nx = kt + 2;
        if (nx < ktpt) issue(nx);
        else CP_COMMIT();

#pragma unroll
        for (int ks2 = 0; ks2 < 2; ks2++) {
            int ks = kw * 2 + ks2;
            uint32_t a[4][4];
            uint32_t b[4][2];
#pragma unroll
            for (int mi = 0; mi < 4; mi++)
                ldsm_x4(a[mi][0], a[mi][1], a[mi][2], a[mi][3],
                        s0 + (uint32_t)(wm * 64 + mi * 16 + arow) * RB1 +
                            ks * 32 + akb);
#pragma unroll
            for (int nb = 0; nb < 2; nb++)
                ldsm_x4(b[2 * nb][0], b[2 * nb][1], b[2 * nb + 1][0],
                        b[2 * nb + 1][1],
                        s0 + TILEB1 +
                            (uint32_t)(wn * 32 + nb * 16 + brow) * RB1 +
                            ks * 32 + bkb);
#pragma unroll
            for (int mi = 0; mi < 4; mi++)
#pragma unroll
                for (int ni = 0; ni < 4; ni++)
                    mma16816(acc[mi][ni], a[mi], b[ni]);
        }
    }
    CP_WAIT0();
    __syncthreads();  // pipeline smem now dead -> reuse as reduction buffer

    // split-K reduction: kw=1 dumps acc; kw=0 adds it in.
    float* red = (float*)smem;   // w2 regions of 2048 floats (8KB) = 64KB
    if (kw == 1) {
#pragma unroll
        for (int mi = 0; mi < 4; mi++)
#pragma unroll
            for (int ni = 0; ni < 4; ni++)
                *(float4*)(red + w2 * 2048 + (mi * 4 + ni) * 128 + lane * 4) =
                    make_float4(acc[mi][ni][0], acc[mi][ni][1],
                                acc[mi][ni][2], acc[mi][ni][3]);
    }
    __syncthreads();

    if (kw == 0) {
        const int g = lane >> 2;
        const int tc = lane & 3;
        const int mirror = (int)blockIdx.x != (int)blockIdx.y;
        const float k1 = g_coef[0] * s_f;
#pragma unroll
        for (int mi = 0; mi < 4; mi++) {
#pragma unroll
            for (int ni = 0; ni < 4; ni++) {
                float4 o = *(float4*)(red + w2 * 2048 + (mi * 4 + ni) * 128 +
                                      lane * 4);
                float v[4];
                v[0] = k1 * (acc[mi][ni][0] + o.x);
                v[1] = k1 * (acc[mi][ni][1] + o.y);
                v[2] = k1 * (acc[mi][ni][2] + o.z);
                v[3] = k1 * (acc[mi][ni][3] + o.w);
#pragma unroll
                for (int half = 0; half < 2; half++) {
                    int row = bm + wm * 64 + mi * 16 + g + half * 8;
                    int col = bn + wn * 32 + ni * 8 + tc * 2;
                    uint32_t H = pack_h2(v[half * 2 + 0], v[half * 2 + 1]);
                    *(uint32_t*)(Hout + (size_t)row * N + col) = H;
                    if (mirror) {
                        *(unsigned short*)(Hout + (size_t)col * N + row) =
                            (unsigned short)(H & 0xffff);
                        *(unsigned short*)(Hout + (size_t)(col + 1) * N + row) =
                            (unsigned short)(H >> 16);
                    }
                }
            }
        }
    }
}

// ---------------------------------------------------------------------------
// GEMM3 (proven config): out = qh @ Ph * s_f
// NT1, KT64, RB144, 3-stage, 256 threads, 2 CTAs/SM. ~420 TF/s measured.
// ---------------------------------------------------------------------------
#define RB3 144
#define TILEB3 (128 * RB3)
#define STAGEB3 (2 * TILEB3)             // Ah, Bh
#define SMEM3 (3 * STAGEB3)              // 110592

__global__ void __launch_bounds__(256, 2) gemm_qp_256(
    const __half* __restrict__ Ah, const __half* __restrict__ Bh,
    int K, float* __restrict__ Fout, int N, float s_f) {
    extern __shared__ char smem[];
    const uint32_t smem_u = smem_to_u32(smem);
    const int tid = threadIdx.x;
    const int lane = tid & 31;
    const int warp = tid >> 5;
    const int wm = warp & 1;
    const int wn = warp >> 1;
    const int bm = blockIdx.y * 128;
    const int bn = blockIdx.x * 128;
    const int ktpt = K / 64;

    float acc[4][4][4];
#pragma unroll
    for (int mi = 0; mi < 4; mi++)
#pragma unroll
        for (int ni = 0; ni < 4; ni++)
#pragma unroll
            for (int c = 0; c < 4; c++) acc[mi][ni][c] = 0.f;

    const int cr = tid >> 3;        // 0..31 (4 passes -> 0..127)
    const int cc = tid & 7;

    auto issue = [&](int kt) {
        int k0 = kt * 64;
        uint32_t s = smem_u + (kt % 3) * STAGEB3;
#pragma unroll
        for (int i = 0; i < 4; i++) {
            int r = cr + i * 32;
            cp_async16(s + r * RB3 + cc * 16,
                       Ah + (size_t)(bm + r) * K + k0 + cc * 8);
        }
#pragma unroll
        for (int i = 0; i < 4; i++) {
            int r = cr + i * 32;
            cp_async16(s + TILEB3 + r * RB3 + cc * 16,
                       Bh + (size_t)(bn + r) * K + k0 + cc * 8);
        }
        CP_COMMIT();
    };

    issue(0);
    issue(1);

    const int arow = lane & 15;
    const int akb = (lane >> 4) * 16;
    const int brow = (lane & 7) + ((lane >> 4) << 3);
    const int bkb = ((lane >> 3) & 1) * 16;

    for (int kt = 0; kt < ktpt; kt++) {
        CP_WAIT1();
        __syncthreads();
        uint32_t s0 = smem_u + (kt % 3) * STAGEB3;

        int nx = kt + 2;
        if (nx < ktpt) issue(nx);
        else CP_COMMIT();

#pragma unroll
        for (int ks = 0; ks < 4; ks++) {
            uint32_t a[4][4];
            uint32_t b[4][2];
#pragma unroll
            for (int mi = 0; mi < 4; mi++)
                ldsm_x4(a[mi][0], a[mi][1], a[mi][2], a[mi][3],
                        s0 + (uint32_t)(wm * 64 + mi * 16 + arow) * RB3 +
                            ks * 32 + akb);
#pragma unroll
            for (int nb = 0; nb < 2; nb++)
                ldsm_x4(b[2 * nb][0], b[2 * nb][1], b[2 * nb + 1][0],
                        b[2 * nb + 1][1],
                        s0 + TILEB3 +
                            (uint32_t)(wn * 32 + nb * 16 + brow) * RB3 +
                            ks * 32 + bkb);
#pragma unroll
            for (int mi = 0; mi < 4; mi++)
#pragma unroll
                for (int ni = 0; ni < 4; ni++)
                    mma16816(acc[mi][ni], a[mi], b[ni]);
        }
    }
    CP_WAIT0();

    const int g = lane >> 2;
    const int tc = lane & 3;
#pragma unroll
    for (int mi = 0; mi < 4; mi++) {
#pragma unroll
        for (int ni = 0; ni < 4; ni++) {
#pragma unroll
            for (int half = 0; half < 2; half++) {
                int row = bm + wm * 64 + mi * 16 + g + half * 8;
                int col = bn + wn * 32 + ni * 8 + tc * 2;
                size_t off = (size_t)row * N + col;
                *(float2*)(Fout + off) =
                    make_float2(s_f * acc[mi][ni][half * 2 + 0],
                                s_f * acc[mi][ni][half * 2 + 1]);
            }
        }
    }
}

// ---------------------------------------------------------------------------
// Launch: retrieved = qh @ (256*alpha*G), G ~= Ah.Ah^T (1-term SYRK).
// ---------------------------------------------------------------------------
extern "C" void kernel_launch(void* const* d_in, const int* in_sizes, int n_in,
                              void* d_out, int out_size) {
    const float* query = (const float*)d_in[0];      // (B, C)
    const float* A = (const float*)d_in[1];          // (K, C)
    const float* log_scale = (const float*)d_in[2];  // scalar
    float* out = (float*)d_out;                      // (B, C)

    __half *AhT, *qh, *Ph;
    cudaGetSymbolAddress((void**)&AhT, g_AhT);
    cudaGetSymbolAddress((void**)&qh, g_qh);
    cudaGetSymbolAddress((void**)&Ph, g_Ph);

    cudaFuncSetAttribute((const void*)gemm_sym_512,
                         cudaFuncAttributeMaxDynamicSharedMemorySize, SMEM1);
    cudaFuncSetAttribute((const void*)gemm_qp_256,
                         cudaFuncAttributeMaxDynamicSharedMemorySize, SMEM3);

    // 1) operand prep (fused ||A||^2 partials) + alpha
    convert_transpose_kernel<<<dim3(C_DIM / 32, K_DIM / 32), 256>>>(A, AhT);
    finalize_alpha_kernel<<<1, 1024>>>(log_scale);
    convert_kernel<<<4096, 256>>>(query, qh, (B_DIM * C_DIM) / 4);

    // 2) Ph = fp16(8192*256*alpha*G), 1-term split-K SYRK, triangle + mirror
    gemm_sym_512<<<dim3(C_DIM / 128, C_DIM / 128), 512, SMEM1>>>(
        AhT, AhT, K_DIM, Ph, C_DIM, 1.0f / 4096.0f);

    // 3) out = qh @ Ph * 2^-13
    gemm_qp_256<<<dim3(C_DIM / 128, B_DIM / 128), 256, SMEM3>>>(
        qh, Ph, C_DIM, out, C_DIM, 1.0f / 8192.0f);
}